// round 5
// baseline (speedup 1.0000x reference)
#include <cuda_runtime.h>

#define NQ 22
#define DIM (1u << 22)

// ---------------- device scratch (static: no allocation) ----------------
__device__ float g_psi0[DIM];          // logical state 0 (real amplitudes)
__device__ float g_psi1[DIM];          // logical state 1
__device__ float g_cs1[NQ][2];         // layer-2 cos/sin of theta/2
__device__ float g_Thi[2048];          // product table, x bits 11..21 (qubits 10..0)
__device__ float g_Tlo[2][2048];       // product table, x bits 0..10 (qubits 21..11)
__device__ float g_part[1024 * 110];   // per-tile partial sums

__device__ __forceinline__ float wred(float v) {
    #pragma unroll
    for (int o = 16; o; o >>= 1) v += __shfl_xor_sync(0xffffffffu, v, o);
    return v;
}

// ---------------- kernel 1: angles + product tables ----------------
__global__ void k_prep(const float* __restrict__ theta) {
    __shared__ float cs0[NQ][2];
    int t = threadIdx.x;
    if (t < NQ) {
        float h0 = 0.5f * theta[t];
        cs0[t][0] = cosf(h0);
        cs0[t][1] = sinf(h0);
        float h1 = 0.5f * theta[NQ + t];
        g_cs1[t][0] = cosf(h1);
        g_cs1[t][1] = sinf(h1);
    }
    __syncthreads();
    for (int v = t; v < 2048; v += blockDim.x) {
        float ph = 1.f;
        #pragma unroll
        for (int k = 0; k < 11; k++) {
            int q = 10 - k;
            int bit = (v >> k) & 1;
            ph *= cs0[q][bit];
        }
        g_Thi[v] = ph;
        float p0 = 1.f, p1 = 1.f;
        #pragma unroll
        for (int k = 0; k < 11; k++) {
            int q = 21 - k;
            int bit = (v >> k) & 1;
            float f = cs0[q][bit];
            p0 *= f;
            float f1 = (q == 21) ? (bit ? cs0[21][0] : -cs0[21][1]) : f;
            p1 *= f1;
        }
        g_Tlo[0][v] = p0;
        g_Tlo[1][v] = p1;
    }
}

// ---------------- kernel 2: state gen + layer-2 RY on bits 12..0 ----------------
__global__ void k_genA() {
    __shared__ float s[8192];
    int bx = blockIdx.x;
    int st = bx >> 9;
    unsigned base = (unsigned)(bx & 511) << 13;
    const float* __restrict__ Tlo = g_Tlo[st];
    int t = threadIdx.x;                 // 512

    for (int off = t; off < 8192; off += 512) {
        unsigned y = base + (unsigned)off;
        unsigned x = (y ^ (y >> 1)) ^ ((y & 1u) * 0x300000u);
        s[off] = __ldg(&g_Thi[x >> 11]) * __ldg(&Tlo[x & 2047u]);
    }
    __syncthreads();

    for (int b = 12; b >= 0; b--) {
        int q = 21 - b;
        float c = g_cs1[q][0], sn = g_cs1[q][1];
        unsigned lowm = (1u << b) - 1u;
        for (int p = t; p < 4096; p += 512) {
            unsigned o0 = (((unsigned)p & ~lowm) << 1) | ((unsigned)p & lowm);
            unsigned o1 = o0 | (1u << b);
            float a0 = s[o0], a1 = s[o1];
            s[o0] = c * a0 - sn * a1;
            s[o1] = sn * a0 + c * a1;
        }
        __syncthreads();
    }

    float* __restrict__ g = st ? g_psi1 : g_psi0;
    for (int off = t; off < 8192; off += 512)
        g[base + off] = s[off];
}

// ---------------- kernel 3: layer-2 RY on bits 13..21 ----------------
__global__ void k_passB() {
    __shared__ float s[512 * 17];
    int bx = blockIdx.x;
    int st = bx >> 9;
    unsigned mid = (unsigned)(bx & 511) << 4;
    float* __restrict__ g = st ? g_psi1 : g_psi0;
    int t = threadIdx.x;                 // 512

    for (int i = t; i < 8192; i += 512) {
        int hi = i >> 4, lo = i & 15;
        s[hi * 17 + lo] = g[((unsigned)hi << 13) | mid | (unsigned)lo];
    }
    __syncthreads();

    for (int bb = 0; bb <= 8; bb++) {
        int q = 8 - bb;
        float c = g_cs1[q][0], sn = g_cs1[q][1];
        unsigned lowm = (1u << bb) - 1u;
        for (int p = t; p < 4096; p += 512) {
            int ph = p >> 4, lo = p & 15;
            unsigned h0 = (((unsigned)ph & ~lowm) << 1) | ((unsigned)ph & lowm);
            unsigned h1 = h0 | (1u << bb);
            float a0 = s[h0 * 17 + lo], a1 = s[h1 * 17 + lo];
            s[h0 * 17 + lo] = c * a0 - sn * a1;
            s[h1 * 17 + lo] = sn * a0 + c * a1;
        }
        __syncthreads();
    }

    for (int i = t; i < 8192; i += 512) {
        int hi = i >> 4, lo = i & 15;
        g[((unsigned)hi << 13) | mid | (unsigned)lo] = s[hi * 17 + lo];
    }
}

// ---------------- kernel 4: restructured Pauli reductions ----------------
// sacc layout: [0]=Se [1]=Sf ; [2+2k],[3+2k] k=0..11 nested-suffix Z sums ;
// [26+3j] j=0..10 in-tile X (m=10+j): ad,a01,bt ;
// [59+3j] j=0..8 cross X halved (m=1+j): ad,u,v ;
// [86..88] m=0: ad,t,bt ; [89..91] m=21: ad,t,bt
#define RTH 256
#define NACC 92

__global__ void k_reduce() {
    __shared__ float s0[4096];
    __shared__ float s1[4096];
    __shared__ float sacc[8][NACC + 4];
    unsigned tile = blockIdx.x;
    unsigned base = tile << 12;
    int t = threadIdx.x, w = t >> 5, lane = t & 31;

    for (int o = t; o < 4096; o += RTH) {
        s0[o] = g_psi0[base + o];
        s1[o] = g_psi1[base + o];
    }
    __syncthreads();

    // ---- Loop A: Z sums (suffix-parity scan gives all 12 signs) ----
    {
        float Se = 0.f, Sf = 0.f, Sze[12], Szf[12];
        #pragma unroll
        for (int k = 0; k < 12; k++) { Sze[k] = 0.f; Szf[k] = 0.f; }
        for (int o = t; o < 4096; o += RTH) {
            float v0 = s0[o], v1 = s1[o];
            unsigned ww = (unsigned)o;
            ww ^= ww >> 1; ww ^= ww >> 2; ww ^= ww >> 4; ww ^= ww >> 8;
            float e = v0 * v0 - v1 * v1, f = v0 * v1;
            Se += e; Sf += f;
            unsigned ei = __float_as_uint(e), fi = __float_as_uint(f);
            #pragma unroll
            for (int k = 0; k < 12; k++) {
                unsigned sb = (ww << (31 - k)) & 0x80000000u;
                Sze[k] += __uint_as_float(ei ^ sb);
                Szf[k] += __uint_as_float(fi ^ sb);
            }
        }
        Se = wred(Se); Sf = wred(Sf);
        if (!lane) { sacc[w][0] = Se; sacc[w][1] = Sf; }
        #pragma unroll
        for (int k = 0; k < 12; k++) {
            float a = wred(Sze[k]), b = wred(Szf[k]);
            if (!lane) { sacc[w][2 + 2 * k] = a; sacc[w][3 + 2 * k] = b; }
        }
    }

    // ---- Loop B: in-tile X, m = 10..20 (d = 3<<(10-j), all in low 12 bits) ----
    {
        float AD[11], A01[11], BT[11];
        #pragma unroll
        for (int j = 0; j < 11; j++) { AD[j] = 0.f; A01[j] = 0.f; BT[j] = 0.f; }
        for (int o = t; o < 4096; o += RTH) {
            float v0 = s0[o], v1 = s1[o];
            unsigned ww = (unsigned)o;
            ww ^= ww >> 1; ww ^= ww >> 2; ww ^= ww >> 4; ww ^= ww >> 8;
            #pragma unroll
            for (int j = 0; j < 11; j++) {
                int po = o ^ (3 << (10 - j));
                float p0 = s0[po], p1 = s1[po];
                AD[j] += v0 * p0 - v1 * p1;
                float tt = v0 * p1;
                A01[j] += tt;
                unsigned sb = (ww << (20 + j)) & 0x80000000u;   // bit (11-j) of ww
                BT[j] += __uint_as_float(__float_as_uint(tt) ^ sb);
            }
        }
        #pragma unroll
        for (int j = 0; j < 11; j++) {
            float a = wred(AD[j]), b = wred(A01[j]), c = wred(BT[j]);
            if (!lane) {
                sacc[w][26 + 3 * j] = a;
                sacc[w][27 + 3 * j] = b;
                sacc[w][28 + 3 * j] = c;
            }
        }
    }

    // ---- Loop C: cross-tile X, m = 0..9 and 21 ----
    {
        float CAD[9], CU[9], CV[9];
        #pragma unroll
        for (int j = 0; j < 9; j++) { CAD[j] = 0.f; CU[j] = 0.f; CV[j] = 0.f; }
        float AD0 = 0.f, T0 = 0.f, BT0 = 0.f;
        float AD21 = 0.f, T21 = 0.f, BT21 = 0.f;

        for (int o = t; o < 4096; o += RTH) {
            float v0 = s0[o], v1 = s1[o];
            unsigned wsb = ((unsigned)(__popc((unsigned)o & 0xFFFu) & 1)) << 31;
            // m = 0 : d = bits 20,21
            {
                unsigned gi = (base ^ 0x300000u) | (unsigned)o;
                float p0 = __ldg(&g_psi0[gi]), p1 = __ldg(&g_psi1[gi]);
                AD0 += v0 * p0 - v1 * p1;
                float tt = v0 * p1;
                T0 += tt;
                BT0 += __uint_as_float(__float_as_uint(tt) ^ wsb);
            }
            // m = 21 : d = bits 0,20,21
            {
                unsigned gi = (base ^ 0x300000u) | ((unsigned)o ^ 1u);
                float p0 = __ldg(&g_psi0[gi]), p1 = __ldg(&g_psi1[gi]);
                AD21 += v0 * p0 - v1 * p1;
                float tt = v0 * p1;
                T21 += tt;
                BT21 += __uint_as_float(__float_as_uint(tt) ^ wsb);
            }
            // m = 1..9, halved: only tiles with bit (21-m) clear, weight 2
            #pragma unroll
            for (int j = 0; j < 9; j++) {
                int m = j + 1;
                unsigned d = 3u << (20 - m);
                if ((base & (1u << (21 - m))) == 0u) {
                    unsigned gi = (base ^ (d & ~0xFFFu)) | ((unsigned)o ^ (d & 0xFFFu));
                    float p0 = __ldg(&g_psi0[gi]), p1 = __ldg(&g_psi1[gi]);
                    CAD[j] += v0 * p0 - v1 * p1;
                    CU[j]  += v0 * p1;
                    CV[j]  += p0 * v1;
                }
            }
        }
        #pragma unroll
        for (int j = 0; j < 9; j++) {
            float a = wred(CAD[j]), b = wred(CU[j]), c = wred(CV[j]);
            if (!lane) {
                sacc[w][59 + 3 * j] = a;
                sacc[w][60 + 3 * j] = b;
                sacc[w][61 + 3 * j] = c;
            }
        }
        AD0 = wred(AD0); T0 = wred(T0); BT0 = wred(BT0);
        AD21 = wred(AD21); T21 = wred(T21); BT21 = wred(BT21);
        if (!lane) {
            sacc[w][86] = AD0;  sacc[w][87] = T0;  sacc[w][88] = BT0;
            sacc[w][89] = AD21; sacc[w][90] = T21; sacc[w][91] = BT21;
        }
    }
    __syncthreads();

    // column sum across 8 warps
    if (t < NACC) {
        float a = 0.f;
        #pragma unroll
        for (int r = 0; r < 8; r++) a += sacc[r][t];
        sacc[0][t] = a;
    }
    __syncthreads();

    // epilogue: per-qubit outputs with tile-base signs
    if (t < 22) {
        int m = t;
        const float* S = sacc[0];
        unsigned Pm = (m == 0) ? 0x1FFFFFu : (((1u << (m + 1)) - 1u) << (21 - m));
        float s = (__popc(base & Pm) & 1) ? -1.f : 1.f;  // base has no low-12 bits
        float cd, c01, ad, a01, b01;
        if (m >= 1 && m <= 9) {
            cd = s * S[0]; c01 = s * S[1];
            int j = m - 1;
            if (base & (1u << (21 - m))) {
                ad = 0.f; a01 = 0.f; b01 = 0.f;
            } else {
                float u = S[60 + 3 * j], v = S[61 + 3 * j];
                ad = 2.f * S[59 + 3 * j];
                a01 = u + v;
                b01 = -s * (u - v);
            }
        } else if (m >= 10 && m <= 20) {
            int k = 21 - m, j = m - 10;
            cd = s * S[2 + 2 * k]; c01 = s * S[3 + 2 * k];
            ad = S[26 + 3 * j]; a01 = S[27 + 3 * j]; b01 = -s * S[28 + 3 * j];
        } else if (m == 0) {
            cd = s * S[2]; c01 = s * S[3];
            ad = S[86]; a01 = S[87]; b01 = -s * S[88];
        } else { // m == 21
            cd = s * S[2]; c01 = s * S[3];
            ad = S[89]; a01 = S[90]; b01 = -s * S[91];
        }
        float* pp = &g_part[tile * 110 + (unsigned)m * 5];
        pp[0] = ad; pp[1] = a01; pp[2] = b01; pp[3] = cd; pp[4] = c01;
    }
}

// ---------------- kernel 5: final combine ----------------
__global__ void k_final(float* __restrict__ out) {
    __shared__ float sums[110];
    int t = threadIdx.x;                 // 1024
    int w = t >> 5, lane = t & 31;
    for (int v = w; v < 110; v += 32) {
        float acc = 0.f;
        for (int tile = lane; tile < 1024; tile += 32)
            acc += g_part[tile * 110 + v];
        acc = wred(acc);
        if (!lane) sums[v] = acc;
    }
    __syncthreads();
    if (t == 0) {
        float loss = 0.f;
        for (int m = 0; m < 22; m++) {
            float ad  = sums[m * 5 + 0];
            float a01 = sums[m * 5 + 1];
            float b01 = sums[m * 5 + 2];
            float cd  = sums[m * 5 + 3];
            float c01 = sums[m * 5 + 4];
            loss += 0.5f * ad * ad + 2.f * a01 * a01
                  + 2.f * b01 * b01
                  + 0.5f * cd * cd + 2.f * c01 * c01;
        }
        out[0] = loss;
    }
}

extern "C" void kernel_launch(void* const* d_in, const int* in_sizes, int n_in,
                              void* d_out, int out_size) {
    const float* theta = (const float*)d_in[0];
    (void)in_sizes; (void)n_in; (void)out_size;
    k_prep<<<1, 1024>>>(theta);
    k_genA<<<1024, 512>>>();
    k_passB<<<1024, 512>>>();
    k_reduce<<<1024, RTH>>>();
    k_final<<<1, 1024>>>((float*)d_out);
}

// round 6
// speedup vs baseline: 1.7579x; 1.7579x over previous
#include <cuda_runtime.h>

#define NQ 22
#define DIM (1u << 22)

// ---------------- device scratch (static: no allocation) ----------------
__device__ float g_psi0[DIM];
__device__ float g_psi1[DIM];
__device__ float g_cs1[NQ][2];
__device__ float g_Thi[2048];
__device__ float g_Tlo[2][2048];
__device__ float g_part[1024 * 110];

__device__ __forceinline__ float wred(float v) {
    #pragma unroll
    for (int o = 16; o; o >>= 1) v += __shfl_xor_sync(0xffffffffu, v, o);
    return v;
}
__device__ __forceinline__ float sgnx(float v, unsigned sb) {
    return __uint_as_float(__float_as_uint(v) ^ sb);
}
__device__ __forceinline__ float sf8(const float* y) {
    return ((y[0]-y[1]) - (y[2]-y[3])) - ((y[4]-y[5]) - (y[6]-y[7]));
}
__device__ __forceinline__ float sf4(const float* y) {
    return (y[0]-y[1]) - (y[2]-y[3]);
}

// ---------------- kernel 1: angles + product tables ----------------
__global__ void k_prep(const float* __restrict__ theta) {
    __shared__ float cs0[NQ][2];
    int t = threadIdx.x;
    if (t < NQ) {
        float h0 = 0.5f * theta[t];
        cs0[t][0] = cosf(h0);
        cs0[t][1] = sinf(h0);
        float h1 = 0.5f * theta[NQ + t];
        g_cs1[t][0] = cosf(h1);
        g_cs1[t][1] = sinf(h1);
    }
    __syncthreads();
    for (int v = t; v < 2048; v += blockDim.x) {
        float ph = 1.f;
        #pragma unroll
        for (int k = 0; k < 11; k++) {
            int q = 10 - k;
            int bit = (v >> k) & 1;
            ph *= cs0[q][bit];
        }
        g_Thi[v] = ph;
        float p0 = 1.f, p1 = 1.f;
        #pragma unroll
        for (int k = 0; k < 11; k++) {
            int q = 21 - k;
            int bit = (v >> k) & 1;
            float f = cs0[q][bit];
            p0 *= f;
            float f1 = (q == 21) ? (bit ? cs0[21][0] : -cs0[21][1]) : f;
            p1 *= f1;
        }
        g_Tlo[0][v] = p0;
        g_Tlo[1][v] = p1;
    }
}

// ---------------- kernel 2: state gen + layer-2 RY on bits 12..0 ----------------
__global__ void k_genA() {
    __shared__ float s[8192];
    int bx = blockIdx.x;
    int st = bx >> 9;
    unsigned base = (unsigned)(bx & 511) << 13;
    const float* __restrict__ Tlo = g_Tlo[st];
    int t = threadIdx.x;                 // 512

    for (int off = t; off < 8192; off += 512) {
        unsigned y = base + (unsigned)off;
        unsigned x = (y ^ (y >> 1)) ^ ((y & 1u) * 0x300000u);
        s[off] = __ldg(&g_Thi[x >> 11]) * __ldg(&Tlo[x & 2047u]);
    }
    __syncthreads();

    for (int b = 12; b >= 0; b--) {
        int q = 21 - b;
        float c = g_cs1[q][0], sn = g_cs1[q][1];
        unsigned lowm = (1u << b) - 1u;
        for (int p = t; p < 4096; p += 512) {
            unsigned o0 = (((unsigned)p & ~lowm) << 1) | ((unsigned)p & lowm);
            unsigned o1 = o0 | (1u << b);
            float a0 = s[o0], a1 = s[o1];
            s[o0] = c * a0 - sn * a1;
            s[o1] = sn * a0 + c * a1;
        }
        __syncthreads();
    }

    float* __restrict__ g = st ? g_psi1 : g_psi0;
    float4* __restrict__ g4 = (float4*)(g + base);
    const float4* s4 = (const float4*)s;
    for (int v = t; v < 2048; v += 512)
        g4[v] = s4[v];
}

// ---------------- kernel 3: layer-2 RY on bits 13..21 ----------------
__global__ void k_passB() {
    __shared__ float s[512 * 17];
    int bx = blockIdx.x;
    int st = bx >> 9;
    unsigned mid = (unsigned)(bx & 511) << 4;
    float* __restrict__ g = st ? g_psi1 : g_psi0;
    const float4* __restrict__ G4 = (const float4*)g;
    float4* __restrict__ GW4 = (float4*)g;
    int t = threadIdx.x;                 // 512

    for (int v = t; v < 2048; v += 512) {
        int hi = v >> 2, q = v & 3;
        float4 d = G4[((unsigned)hi << 11) + (mid >> 2) + (unsigned)q];
        int sb = hi * 17 + q * 4;
        s[sb + 0] = d.x; s[sb + 1] = d.y; s[sb + 2] = d.z; s[sb + 3] = d.w;
    }
    __syncthreads();

    for (int bb = 0; bb <= 8; bb++) {
        int q = 8 - bb;
        float c = g_cs1[q][0], sn = g_cs1[q][1];
        unsigned lowm = (1u << bb) - 1u;
        for (int p = t; p < 4096; p += 512) {
            int ph = p >> 4, lo = p & 15;
            unsigned h0 = (((unsigned)ph & ~lowm) << 1) | ((unsigned)ph & lowm);
            unsigned h1 = h0 | (1u << bb);
            float a0 = s[h0 * 17 + lo], a1 = s[h1 * 17 + lo];
            s[h0 * 17 + lo] = c * a0 - sn * a1;
            s[h1 * 17 + lo] = sn * a0 + c * a1;
        }
        __syncthreads();
    }

    for (int v = t; v < 2048; v += 512) {
        int hi = v >> 2, q = v & 3;
        int sb = hi * 17 + q * 4;
        float4 d = make_float4(s[sb + 0], s[sb + 1], s[sb + 2], s[sb + 3]);
        GW4[((unsigned)hi << 11) + (mid >> 2) + (unsigned)q] = d;
    }
}

// ---------------- kernel 4: register-blocked Pauli reductions ----------------
// Each of 256 threads owns chunk c=t: elements o = c*16 + i (i=0..15) in regs.
// sacc slots: 0=Se 1=Sf ; 2+k / 14+k : Z e/f (k=0..11) ;
// 26+3j (j=m-10, m=10..20): ad, a01, W ;
// 59+3(m-1) (m=1..9): AD,U,V ; 86..89: m=0 AD,U,V,W ; 90..93: m=21 AD,U,V,W
__global__ void __launch_bounds__(256) k_reduce() {
    __shared__ float s0[4096];
    __shared__ float s1[4096];
    __shared__ float sacc[8][96];
    unsigned tile = blockIdx.x;
    unsigned base = tile << 12;
    int t = threadIdx.x, w = t >> 5, lane = t & 31;
    int c = t;

    float r0[16], r1[16];
    {
        const float4* G0 = (const float4*)(g_psi0 + base);
        const float4* G1 = (const float4*)(g_psi1 + base);
        float4* S0 = (float4*)s0;
        float4* S1 = (float4*)s1;
        #pragma unroll
        for (int q = 0; q < 4; q++) {
            float4 a = G0[c * 4 + q]; S0[c * 4 + q] = a;
            r0[q*4+0] = a.x; r0[q*4+1] = a.y; r0[q*4+2] = a.z; r0[q*4+3] = a.w;
            float4 b = G1[c * 4 + q]; S1[c * 4 + q] = b;
            r1[q*4+0] = b.x; r1[q*4+1] = b.y; r1[q*4+2] = b.z; r1[q*4+3] = b.w;
        }
    }
    unsigned H = ((unsigned)(__popc(t & 0xFF) & 1)) << 31;

    // ---- Z sums via in-chunk folding ----
    #define ZFOLD(EXPR, IDXBASE, TOTIDX) { \
        float x[16]; \
        _Pragma("unroll") for (int i = 0; i < 16; i++) x[i] = (EXPR); \
        float s1a[8], d0[8]; \
        _Pragma("unroll") for (int j = 0; j < 8; j++) { \
            s1a[j] = x[2*j] + x[2*j+1]; d0[j] = x[2*j] - x[2*j+1]; } \
        float D0 = sf8(d0), D1 = sf8(s1a); \
        float s2[4]; \
        _Pragma("unroll") for (int j = 0; j < 4; j++) s2[j] = s1a[2*j] + s1a[2*j+1]; \
        float D2 = sf4(s2); \
        float s3a = s2[0] + s2[1], s3b = s2[2] + s2[3]; \
        float D3 = s3a - s3b, T = s3a + s3b; \
        float v; \
        v = wred(sgnx(D0, H)); if (!lane) sacc[w][(IDXBASE)+0] = v; \
        v = wred(sgnx(D1, H)); if (!lane) sacc[w][(IDXBASE)+1] = v; \
        v = wred(sgnx(D2, H)); if (!lane) sacc[w][(IDXBASE)+2] = v; \
        v = wred(sgnx(D3, H)); if (!lane) sacc[w][(IDXBASE)+3] = v; \
        _Pragma("unroll") for (int k = 4; k < 12; k++) { \
            unsigned hk = ((unsigned)(__popc((unsigned)t >> (k-4)) & 1)) << 31; \
            v = wred(sgnx(T, hk)); if (!lane) sacc[w][(IDXBASE)+k] = v; } \
        v = wred(T); if (!lane) sacc[w][TOTIDX] = v; }

    ZFOLD(r0[i]*r0[i] - r1[i]*r1[i], 2, 0)
    ZFOLD(r0[i]*r1[i], 14, 1)
    #undef ZFOLD

    // ---- in-register masks m=18,19,20 (d bits within i) ----
    #define INREG(MM, MSK, PB) { \
        float ad = 0.f, us = 0.f, wr = 0.f; \
        _Pragma("unroll") for (int i = 0; i < 16; i++) { \
            float p0 = r0[i ^ (MSK)], p1 = r1[i ^ (MSK)]; \
            ad += r0[i]*p0 - r1[i]*p1; \
            float u = r0[i]*p1; us += u; \
            if (__popc(i >> (PB)) & 1) wr -= u; else wr += u; } \
        float v = wred(ad); if (!lane) sacc[w][26+3*((MM)-10)+0] = v; \
        v = wred(us);       if (!lane) sacc[w][26+3*((MM)-10)+1] = v; \
        v = wred(sgnx(wr, H)); if (!lane) sacc[w][26+3*((MM)-10)+2] = v; }
    INREG(20, 3, 1)
    INREG(19, 6, 2)
    INREG(18, 12, 3)
    #undef INREG

    // ---- shuffle masks m=13..17 (partner chunk within warp) ----
    #define SHFM(MM, LX, IX) { \
        float ad = 0.f, us = 0.f; \
        _Pragma("unroll") for (int i = 0; i < 16; i++) { \
            float p0 = __shfl_xor_sync(0xffffffffu, r0[i ^ (IX)], (LX)); \
            float p1 = __shfl_xor_sync(0xffffffffu, r1[i ^ (IX)], (LX)); \
            ad += r0[i]*p0 - r1[i]*p1; us += r0[i]*p1; } \
        unsigned hs = ((unsigned)(__popc((unsigned)t >> (21-(MM)-4)) & 1)) << 31; \
        float v = wred(ad); if (!lane) sacc[w][26+3*((MM)-10)+0] = v; \
        v = wred(us);       if (!lane) sacc[w][26+3*((MM)-10)+1] = v; \
        v = wred(sgnx(us, hs)); if (!lane) sacc[w][26+3*((MM)-10)+2] = v; }
    SHFM(17, 1, 8)
    SHFM(16, 3, 0)
    SHFM(15, 6, 0)
    SHFM(14, 12, 0)
    SHFM(13, 24, 0)
    #undef SHFM

    __syncthreads();

    // ---- smem masks m=10,11,12 (partner chunk cross-warp) ----
    #define SMEMM(MM, CX) { \
        float ad = 0.f, us = 0.f; \
        const float4* S04 = (const float4*)s0; \
        const float4* S14 = (const float4*)s1; \
        _Pragma("unroll") for (int q = 0; q < 4; q++) { \
            float4 a = S04[(c ^ (CX)) * 4 + q], b = S14[(c ^ (CX)) * 4 + q]; \
            float pa[4] = {a.x, a.y, a.z, a.w}; \
            float pb[4] = {b.x, b.y, b.z, b.w}; \
            _Pragma("unroll") for (int z = 0; z < 4; z++) { \
                int i = q*4 + z; \
                ad += r0[i]*pa[z] - r1[i]*pb[z]; us += r0[i]*pb[z]; } } \
        unsigned hs = ((unsigned)(__popc((unsigned)t >> (21-(MM)-4)) & 1)) << 31; \
        float v = wred(ad); if (!lane) sacc[w][26+3*((MM)-10)+0] = v; \
        v = wred(us);       if (!lane) sacc[w][26+3*((MM)-10)+1] = v; \
        v = wred(sgnx(us, hs)); if (!lane) sacc[w][26+3*((MM)-10)+2] = v; }
    SMEMM(12, 0x30)
    SMEMM(11, 0x60)
    SMEMM(10, 0xC0)
    #undef SMEMM

    // ---- cross-tile masks, halved by pair symmetry ----
    #define CROSSM(SLOT, DH, CH, SWAP, DOW, CONDBIT) \
    if (!(base & (CONDBIT))) { \
        float ad = 0.f, U = 0.f, V = 0.f, wr = 0.f; \
        const float4* P0 = (const float4*)(g_psi0 + (base ^ (DH))); \
        const float4* P1 = (const float4*)(g_psi1 + (base ^ (DH))); \
        _Pragma("unroll") for (int q = 0; q < 4; q++) { \
            float4 a = P0[(c ^ (CH)) * 4 + q], b = P1[(c ^ (CH)) * 4 + q]; \
            float pa[4] = {a.x, a.y, a.z, a.w}; \
            float pb[4] = {b.x, b.y, b.z, b.w}; \
            _Pragma("unroll") for (int z = 0; z < 4; z++) { \
                int i = q*4 + z; int zz = (SWAP) ? (z ^ 1) : z; \
                float p0 = pa[zz], p1 = pb[zz]; \
                ad += r0[i]*p0 - r1[i]*p1; \
                float u = r0[i]*p1, vv = p0*r1[i]; \
                U += u; V += vv; \
                if (DOW) { if (__popc(i) & 1) wr -= (u - vv); else wr += (u - vv); } } } \
        float v = wred(ad); if (!lane) sacc[w][(SLOT)+0] = v; \
        v = wred(U); if (!lane) sacc[w][(SLOT)+1] = v; \
        v = wred(V); if (!lane) sacc[w][(SLOT)+2] = v; \
        if (DOW) { v = wred(sgnx(wr, H)); if (!lane) sacc[w][(SLOT)+3] = v; } }

    CROSSM(86, 0x300000u, 0, 0, 1, 0x200000u)      // m=0
    CROSSM(59, (3u<<19), 0, 0, 0, (1u<<20))        // m=1
    CROSSM(62, (3u<<18), 0, 0, 0, (1u<<19))        // m=2
    CROSSM(65, (3u<<17), 0, 0, 0, (1u<<18))        // m=3
    CROSSM(68, (3u<<16), 0, 0, 0, (1u<<17))        // m=4
    CROSSM(71, (3u<<15), 0, 0, 0, (1u<<16))        // m=5
    CROSSM(74, (3u<<14), 0, 0, 0, (1u<<15))        // m=6
    CROSSM(77, (3u<<13), 0, 0, 0, (1u<<14))        // m=7
    CROSSM(80, (3u<<12), 0, 0, 0, (1u<<13))        // m=8
    CROSSM(83, 0x1000u, 0x80, 0, 0, (1u<<12))      // m=9 (dlow=0x800 -> chunk^0x80)
    CROSSM(90, 0x300000u, 0, 1, 1, 0x200000u)      // m=21 (dlow=1 -> component swap)
    #undef CROSSM

    __syncthreads();

    if (t < 94) {
        float a = 0.f;
        #pragma unroll
        for (int r = 0; r < 8; r++) a += sacc[r][t];
        sacc[0][t] = a;
    }
    __syncthreads();

    // ---- epilogue ----
    if (t < 22) {
        int m = t;
        const float* S = sacc[0];
        unsigned Pm = (m == 0) ? 0x1FFFFFu : (((1u << (m + 1)) - 1u) << (21 - m));
        float s = (__popc(base & Pm) & 1) ? -1.f : 1.f;
        float cd, c01, ad, a01, b01;
        if (m >= 10 && m <= 20) {
            int k = 21 - m, j = m - 10;
            cd = s * S[2 + k]; c01 = s * S[14 + k];
            ad = S[26 + 3*j]; a01 = S[27 + 3*j]; b01 = -s * S[28 + 3*j];
        } else if (m >= 1 && m <= 9) {
            cd = s * S[0]; c01 = s * S[1];
            if (base & (1u << (21 - m))) {
                ad = 0.f; a01 = 0.f; b01 = 0.f;
            } else {
                int sl = 59 + 3 * (m - 1);
                float U = S[sl + 1], V = S[sl + 2];
                ad = 2.f * S[sl];
                a01 = U + V;
                b01 = -s * (U - V);
            }
        } else if (m == 0) {
            cd = s * S[2]; c01 = s * S[14];
            if (base & 0x200000u) { ad = 0.f; a01 = 0.f; b01 = 0.f; }
            else {
                ad = 2.f * S[86];
                a01 = S[87] + S[88];
                b01 = -s * S[89];
            }
        } else { // m == 21
            cd = s * S[2]; c01 = s * S[14];
            if (base & 0x200000u) { ad = 0.f; a01 = 0.f; b01 = 0.f; }
            else {
                ad = 2.f * S[90];
                a01 = S[91] + S[92];
                b01 = -s * S[93];
            }
        }
        float* pp = &g_part[tile * 110 + (unsigned)m * 5];
        pp[0] = ad; pp[1] = a01; pp[2] = b01; pp[3] = cd; pp[4] = c01;
    }
}

// ---------------- kernel 5: final combine ----------------
__global__ void k_final(float* __restrict__ out) {
    __shared__ float sums[110];
    int t = threadIdx.x;                 // 1024
    int w = t >> 5, lane = t & 31;
    for (int v = w; v < 110; v += 32) {
        float acc = 0.f;
        for (int tile = lane; tile < 1024; tile += 32)
            acc += g_part[tile * 110 + v];
        acc = wred(acc);
        if (!lane) sums[v] = acc;
    }
    __syncthreads();
    if (t == 0) {
        float loss = 0.f;
        for (int m = 0; m < 22; m++) {
            float ad  = sums[m * 5 + 0];
            float a01 = sums[m * 5 + 1];
            float b01 = sums[m * 5 + 2];
            float cd  = sums[m * 5 + 3];
            float c01 = sums[m * 5 + 4];
            loss += 0.5f * ad * ad + 2.f * a01 * a01
                  + 2.f * b01 * b01
                  + 0.5f * cd * cd + 2.f * c01 * c01;
        }
        out[0] = loss;
    }
}

extern "C" void kernel_launch(void* const* d_in, const int* in_sizes, int n_in,
                              void* d_out, int out_size) {
    const float* theta = (const float*)d_in[0];
    (void)in_sizes; (void)n_in; (void)out_size;
    k_prep<<<1, 1024>>>(theta);
    k_genA<<<1024, 512>>>();
    k_passB<<<1024, 512>>>();
    k_reduce<<<1024, 256>>>();
    k_final<<<1, 1024>>>((float*)d_out);
}

// round 8
// speedup vs baseline: 2.3506x; 1.3372x over previous
#include <cuda_runtime.h>

#define NQ 22
#define DIM (1u << 22)

// ---------------- device scratch (static: no allocation) ----------------
__device__ float g_psi0[DIM];
__device__ float g_psi1[DIM];
__device__ float g_cs1[NQ][2];
__device__ float g_Thi[2048];
__device__ float g_Tlo[2][2048];
__device__ float g_part[1024 * 110];

__device__ __forceinline__ float wred(float v) {
    #pragma unroll
    for (int o = 16; o; o >>= 1) v += __shfl_xor_sync(0xffffffffu, v, o);
    return v;
}
__device__ __forceinline__ float sgnx(float v, unsigned sb) {
    return __uint_as_float(__float_as_uint(v) ^ sb);
}
__device__ __forceinline__ float sf8(const float* y) {
    return ((y[0]-y[1]) - (y[2]-y[3])) - ((y[4]-y[5]) - (y[6]-y[7]));
}
__device__ __forceinline__ float sf4(const float* y) {
    return (y[0]-y[1]) - (y[2]-y[3]);
}

// ---------------- kernel 1: angles + product tables ----------------
__global__ void k_prep(const float* __restrict__ theta) {
    __shared__ float cs0[NQ][2];
    int t = threadIdx.x;
    if (t < NQ) {
        float h0 = 0.5f * theta[t];
        cs0[t][0] = cosf(h0);
        cs0[t][1] = sinf(h0);
        float h1 = 0.5f * theta[NQ + t];
        g_cs1[t][0] = cosf(h1);
        g_cs1[t][1] = sinf(h1);
    }
    __syncthreads();
    for (int v = t; v < 2048; v += blockDim.x) {
        float ph = 1.f;
        #pragma unroll
        for (int k = 0; k < 11; k++) {
            int q = 10 - k;
            int bit = (v >> k) & 1;
            ph *= cs0[q][bit];
        }
        g_Thi[v] = ph;
        float p0 = 1.f, p1 = 1.f;
        #pragma unroll
        for (int k = 0; k < 11; k++) {
            int q = 21 - k;
            int bit = (v >> k) & 1;
            float f = cs0[q][bit];
            p0 *= f;
            float f1 = (q == 21) ? (bit ? cs0[21][0] : -cs0[21][1]) : f;
            p1 *= f1;
        }
        g_Tlo[0][v] = p0;
        g_Tlo[1][v] = p1;
    }
}

// ---------------- kernel 2: state gen + layer-2 RY on bits 12..0 ----------------
// Register-blocked: 4 bits in regs (qubits 21..18), 5 lane bits (qubits 17..13),
// one swizzled smem exchange, 4 more reg bits (qubits 12..9).
__global__ void __launch_bounds__(512) k_genA() {
    __shared__ float s[8192];
    int bx = blockIdx.x;
    int st = bx >> 9;
    unsigned base = (unsigned)(bx & 511) << 13;
    int t = threadIdx.x;
    int lane = t & 31;

    // stage product tables into smem (reused later as exchange buffer)
    {
        const float4* T4 = (const float4*)g_Thi;
        const float4* L4 = (const float4*)g_Tlo[st];
        float4* S4 = (float4*)s;
        S4[t] = T4[t];            // Thi -> s[0..2047]
        S4[512 + t] = L4[t];      // Tlo -> s[2048..4095]
    }
    __syncthreads();

    float r[16];
    #pragma unroll
    for (int i = 0; i < 16; i++) {
        unsigned y = base + (unsigned)(t * 16 + i);
        unsigned x = (y ^ (y >> 1)) ^ ((y & 1u) * 0x300000u);
        r[i] = s[x >> 11] * s[2048 + (x & 2047u)];
    }

    // in-register stages: element bit br (0..3) -> qubit 21-br
    #pragma unroll
    for (int br = 0; br < 4; br++) {
        int q = 21 - br;
        float c = g_cs1[q][0], sn = g_cs1[q][1];
        #pragma unroll
        for (int i0 = 0; i0 < 16; i0++) if (!(i0 & (1 << br))) {
            int i1 = i0 | (1 << br);
            float a0 = r[i0], a1 = r[i1];
            r[i0] = c * a0 - sn * a1;
            r[i1] = sn * a0 + c * a1;
        }
    }
    // shuffle stages: element bit 4+lb -> qubit 17-lb
    #pragma unroll
    for (int lb = 0; lb < 5; lb++) {
        int q = 17 - lb;
        float c = g_cs1[q][0], sn = g_cs1[q][1];
        float ss = (lane & (1 << lb)) ? sn : -sn;
        #pragma unroll
        for (int i = 0; i < 16; i++) {
            float p = __shfl_xor_sync(0xffffffffu, r[i], 1 << lb);
            r[i] = fmaf(ss, p, c * r[i]);
        }
    }
    __syncthreads();   // tables no longer needed

    // swizzled exchange: rotate bits 9..12 into the register index
    #pragma unroll
    for (int i = 0; i < 16; i++) {
        unsigned o = (unsigned)(t * 16 + i);
        s[o ^ ((o >> 5) & 31u)] = r[i];
    }
    __syncthreads();
    #pragma unroll
    for (int j = 0; j < 16; j++) {
        unsigned o = ((unsigned)j << 9) | (unsigned)t;
        r[j] = s[o ^ ((o >> 5) & 31u)];
    }
    // in-register stages: element bit 9+bj -> qubit 12-bj
    #pragma unroll
    for (int bj = 0; bj < 4; bj++) {
        int q = 12 - bj;
        float c = g_cs1[q][0], sn = g_cs1[q][1];
        #pragma unroll
        for (int j0 = 0; j0 < 16; j0++) if (!(j0 & (1 << bj))) {
            int j1 = j0 | (1 << bj);
            float a0 = r[j0], a1 = r[j1];
            r[j0] = c * a0 - sn * a1;
            r[j1] = sn * a0 + c * a1;
        }
    }
    float* __restrict__ g = st ? g_psi1 : g_psi0;
    #pragma unroll
    for (int j = 0; j < 16; j++)
        g[base + ((unsigned)j << 9) + (unsigned)t] = r[j];
}

// ---------------- kernel 3: layer-2 RY on bits 13..21, register-blocked ----------------
// hi (9 bits) = (j<<5)|lane : 5 lane bits (qubits 8..4) + 4 reg bits (qubits 3..0).
// Warp w (0..15) owns lo offset w. smem touched only for coalesced load/store.
__global__ void __launch_bounds__(512) k_passB() {
    __shared__ float s[512 * 17];
    int bx = blockIdx.x;
    int st = bx >> 9;
    unsigned mid = (unsigned)(bx & 511) << 4;
    float* __restrict__ g = st ? g_psi1 : g_psi0;
    int t = threadIdx.x;
    int lane = t & 31, w = t >> 5;   // w = 0..15

    const float4* G4 = (const float4*)g;
    for (int v = t; v < 2048; v += 512) {
        int hi = v >> 2, q = v & 3;
        float4 d = G4[((unsigned)hi << 11) + (mid >> 2) + (unsigned)q];
        int sb = hi * 17 + q * 4;
        s[sb + 0] = d.x; s[sb + 1] = d.y; s[sb + 2] = d.z; s[sb + 3] = d.w;
    }
    __syncthreads();

    float r[16];
    #pragma unroll
    for (int j = 0; j < 16; j++)
        r[j] = s[((j << 5) | lane) * 17 + w];

    // shuffle stages: hi bit lb -> qubit 8-lb
    #pragma unroll
    for (int lb = 0; lb < 5; lb++) {
        int q = 8 - lb;
        float c = g_cs1[q][0], sn = g_cs1[q][1];
        float ss = (lane & (1 << lb)) ? sn : -sn;
        #pragma unroll
        for (int j = 0; j < 16; j++) {
            float p = __shfl_xor_sync(0xffffffffu, r[j], 1 << lb);
            r[j] = fmaf(ss, p, c * r[j]);
        }
    }
    // in-register stages: hi bit 5+bj -> qubit 3-bj
    #pragma unroll
    for (int bj = 0; bj < 4; bj++) {
        int q = 3 - bj;
        float c = g_cs1[q][0], sn = g_cs1[q][1];
        #pragma unroll
        for (int j0 = 0; j0 < 16; j0++) if (!(j0 & (1 << bj))) {
            int j1 = j0 | (1 << bj);
            float a0 = r[j0], a1 = r[j1];
            r[j0] = c * a0 - sn * a1;
            r[j1] = sn * a0 + c * a1;
        }
    }
    #pragma unroll
    for (int j = 0; j < 16; j++)
        s[((j << 5) | lane) * 17 + w] = r[j];
    __syncthreads();

    float4* GW4 = (float4*)g;
    for (int v = t; v < 2048; v += 512) {
        int hi = v >> 2, q = v & 3;
        int sb = hi * 17 + q * 4;
        float4 d = make_float4(s[sb + 0], s[sb + 1], s[sb + 2], s[sb + 3]);
        GW4[((unsigned)hi << 11) + (mid >> 2) + (unsigned)q] = d;
    }
}

// ---------------- kernel 4: register-blocked Pauli reductions ----------------
__global__ void __launch_bounds__(256) k_reduce() {
    __shared__ float s0[4096];
    __shared__ float s1[4096];
    __shared__ float sacc[8][96];
    unsigned tile = blockIdx.x;
    unsigned base = tile << 12;
    int t = threadIdx.x, w = t >> 5, lane = t & 31;
    int c = t;

    float r0[16], r1[16];
    {
        const float4* G0 = (const float4*)(g_psi0 + base);
        const float4* G1 = (const float4*)(g_psi1 + base);
        float4* S0 = (float4*)s0;
        float4* S1 = (float4*)s1;
        #pragma unroll
        for (int q = 0; q < 4; q++) {
            float4 a = G0[c * 4 + q]; S0[c * 4 + q] = a;
            r0[q*4+0] = a.x; r0[q*4+1] = a.y; r0[q*4+2] = a.z; r0[q*4+3] = a.w;
            float4 b = G1[c * 4 + q]; S1[c * 4 + q] = b;
            r1[q*4+0] = b.x; r1[q*4+1] = b.y; r1[q*4+2] = b.z; r1[q*4+3] = b.w;
        }
    }
    unsigned H = ((unsigned)(__popc(t & 0xFF) & 1)) << 31;

    #define ZFOLD(EXPR, IDXBASE, TOTIDX) { \
        float x[16]; \
        _Pragma("unroll") for (int i = 0; i < 16; i++) x[i] = (EXPR); \
        float s1a[8], d0[8]; \
        _Pragma("unroll") for (int j = 0; j < 8; j++) { \
            s1a[j] = x[2*j] + x[2*j+1]; d0[j] = x[2*j] - x[2*j+1]; } \
        float D0 = sf8(d0), D1 = sf8(s1a); \
        float s2[4]; \
        _Pragma("unroll") for (int j = 0; j < 4; j++) s2[j] = s1a[2*j] + s1a[2*j+1]; \
        float D2 = sf4(s2); \
        float s3a = s2[0] + s2[1], s3b = s2[2] + s2[3]; \
        float D3 = s3a - s3b, T = s3a + s3b; \
        float v; \
        v = wred(sgnx(D0, H)); if (!lane) sacc[w][(IDXBASE)+0] = v; \
        v = wred(sgnx(D1, H)); if (!lane) sacc[w][(IDXBASE)+1] = v; \
        v = wred(sgnx(D2, H)); if (!lane) sacc[w][(IDXBASE)+2] = v; \
        v = wred(sgnx(D3, H)); if (!lane) sacc[w][(IDXBASE)+3] = v; \
        _Pragma("unroll") for (int k = 4; k < 12; k++) { \
            unsigned hk = ((unsigned)(__popc((unsigned)t >> (k-4)) & 1)) << 31; \
            v = wred(sgnx(T, hk)); if (!lane) sacc[w][(IDXBASE)+k] = v; } \
        v = wred(T); if (!lane) sacc[w][TOTIDX] = v; }

    ZFOLD(r0[i]*r0[i] - r1[i]*r1[i], 2, 0)
    ZFOLD(r0[i]*r1[i], 14, 1)
    #undef ZFOLD

    #define INREG(MM, MSK, PB) { \
        float ad = 0.f, us = 0.f, wr = 0.f; \
        _Pragma("unroll") for (int i = 0; i < 16; i++) { \
            float p0 = r0[i ^ (MSK)], p1 = r1[i ^ (MSK)]; \
            ad += r0[i]*p0 - r1[i]*p1; \
            float u = r0[i]*p1; us += u; \
            if (__popc(i >> (PB)) & 1) wr -= u; else wr += u; } \
        float v = wred(ad); if (!lane) sacc[w][26+3*((MM)-10)+0] = v; \
        v = wred(us);       if (!lane) sacc[w][26+3*((MM)-10)+1] = v; \
        v = wred(sgnx(wr, H)); if (!lane) sacc[w][26+3*((MM)-10)+2] = v; }
    INREG(20, 3, 1)
    INREG(19, 6, 2)
    INREG(18, 12, 3)
    #undef INREG

    #define SHFM(MM, LX, IX) { \
        float ad = 0.f, us = 0.f; \
        _Pragma("unroll") for (int i = 0; i < 16; i++) { \
            float p0 = __shfl_xor_sync(0xffffffffu, r0[i ^ (IX)], (LX)); \
            float p1 = __shfl_xor_sync(0xffffffffu, r1[i ^ (IX)], (LX)); \
            ad += r0[i]*p0 - r1[i]*p1; us += r0[i]*p1; } \
        unsigned hs = ((unsigned)(__popc((unsigned)t >> (21-(MM)-4)) & 1)) << 31; \
        float v = wred(ad); if (!lane) sacc[w][26+3*((MM)-10)+0] = v; \
        v = wred(us);       if (!lane) sacc[w][26+3*((MM)-10)+1] = v; \
        v = wred(sgnx(us, hs)); if (!lane) sacc[w][26+3*((MM)-10)+2] = v; }
    SHFM(17, 1, 8)
    SHFM(16, 3, 0)
    SHFM(15, 6, 0)
    SHFM(14, 12, 0)
    SHFM(13, 24, 0)
    #undef SHFM

    __syncthreads();

    #define SMEMM(MM, CX) { \
        float ad = 0.f, us = 0.f; \
        const float4* S04 = (const float4*)s0; \
        const float4* S14 = (const float4*)s1; \
        _Pragma("unroll") for (int q = 0; q < 4; q++) { \
            float4 a = S04[(c ^ (CX)) * 4 + q], b = S14[(c ^ (CX)) * 4 + q]; \
            float pa[4] = {a.x, a.y, a.z, a.w}; \
            float pb[4] = {b.x, b.y, b.z, b.w}; \
            _Pragma("unroll") for (int z = 0; z < 4; z++) { \
                int i = q*4 + z; \
                ad += r0[i]*pa[z] - r1[i]*pb[z]; us += r0[i]*pb[z]; } } \
        unsigned hs = ((unsigned)(__popc((unsigned)t >> (21-(MM)-4)) & 1)) << 31; \
        float v = wred(ad); if (!lane) sacc[w][26+3*((MM)-10)+0] = v; \
        v = wred(us);       if (!lane) sacc[w][26+3*((MM)-10)+1] = v; \
        v = wred(sgnx(us, hs)); if (!lane) sacc[w][26+3*((MM)-10)+2] = v; }
    SMEMM(12, 0x30)
    SMEMM(11, 0x60)
    SMEMM(10, 0xC0)
    #undef SMEMM

    #define CROSSM(SLOT, DH, CH, SWAP, DOW, CONDBIT) \
    if (!(base & (CONDBIT))) { \
        float ad = 0.f, U = 0.f, V = 0.f, wr = 0.f; \
        const float4* P0 = (const float4*)(g_psi0 + (base ^ (DH))); \
        const float4* P1 = (const float4*)(g_psi1 + (base ^ (DH))); \
        _Pragma("unroll") for (int q = 0; q < 4; q++) { \
            float4 a = P0[(c ^ (CH)) * 4 + q], b = P1[(c ^ (CH)) * 4 + q]; \
            float pa[4] = {a.x, a.y, a.z, a.w}; \
            float pb[4] = {b.x, b.y, b.z, b.w}; \
            _Pragma("unroll") for (int z = 0; z < 4; z++) { \
                int i = q*4 + z; int zz = (SWAP) ? (z ^ 1) : z; \
                float p0 = pa[zz], p1 = pb[zz]; \
                ad += r0[i]*p0 - r1[i]*p1; \
                float u = r0[i]*p1, vv = p0*r1[i]; \
                U += u; V += vv; \
                if (DOW) { if (__popc(i) & 1) wr -= (u - vv); else wr += (u - vv); } } } \
        float v = wred(ad); if (!lane) sacc[w][(SLOT)+0] = v; \
        v = wred(U); if (!lane) sacc[w][(SLOT)+1] = v; \
        v = wred(V); if (!lane) sacc[w][(SLOT)+2] = v; \
        if (DOW) { v = wred(sgnx(wr, H)); if (!lane) sacc[w][(SLOT)+3] = v; } }

    CROSSM(86, 0x300000u, 0, 0, 1, 0x200000u)
    CROSSM(59, (3u<<19), 0, 0, 0, (1u<<20))
    CROSSM(62, (3u<<18), 0, 0, 0, (1u<<19))
    CROSSM(65, (3u<<17), 0, 0, 0, (1u<<18))
    CROSSM(68, (3u<<16), 0, 0, 0, (1u<<17))
    CROSSM(71, (3u<<15), 0, 0, 0, (1u<<16))
    CROSSM(74, (3u<<14), 0, 0, 0, (1u<<15))
    CROSSM(77, (3u<<13), 0, 0, 0, (1u<<14))
    CROSSM(80, (3u<<12), 0, 0, 0, (1u<<13))
    CROSSM(83, 0x1000u, 0x80, 0, 0, (1u<<12))
    CROSSM(90, 0x300000u, 0, 1, 1, 0x200000u)
    #undef CROSSM

    __syncthreads();

    if (t < 94) {
        float a = 0.f;
        #pragma unroll
        for (int r = 0; r < 8; r++) a += sacc[r][t];
        sacc[0][t] = a;
    }
    __syncthreads();

    if (t < 22) {
        int m = t;
        const float* S = sacc[0];
        unsigned Pm = (m == 0) ? 0x1FFFFFu : (((1u << (m + 1)) - 1u) << (21 - m));
        float s = (__popc(base & Pm) & 1) ? -1.f : 1.f;
        float cd, c01, ad, a01, b01;
        if (m >= 10 && m <= 20) {
            int k = 21 - m, j = m - 10;
            cd = s * S[2 + k]; c01 = s * S[14 + k];
            ad = S[26 + 3*j]; a01 = S[27 + 3*j]; b01 = -s * S[28 + 3*j];
        } else if (m >= 1 && m <= 9) {
            cd = s * S[0]; c01 = s * S[1];
            if (base & (1u << (21 - m))) {
                ad = 0.f; a01 = 0.f; b01 = 0.f;
            } else {
                int sl = 59 + 3 * (m - 1);
                float U = S[sl + 1], V = S[sl + 2];
                ad = 2.f * S[sl];
                a01 = U + V;
                b01 = -s * (U - V);
            }
        } else if (m == 0) {
            cd = s * S[2]; c01 = s * S[14];
            if (base & 0x200000u) { ad = 0.f; a01 = 0.f; b01 = 0.f; }
            else {
                ad = 2.f * S[86];
                a01 = S[87] + S[88];
                b01 = -s * S[89];
            }
        } else {
            cd = s * S[2]; c01 = s * S[14];
            if (base & 0x200000u) { ad = 0.f; a01 = 0.f; b01 = 0.f; }
            else {
                ad = 2.f * S[90];
                a01 = S[91] + S[92];
                b01 = -s * S[93];
            }
        }
        float* pp = &g_part[tile * 110 + (unsigned)m * 5];
        pp[0] = ad; pp[1] = a01; pp[2] = b01; pp[3] = cd; pp[4] = c01;
    }
}

// ---------------- kernel 5: final combine ----------------
__global__ void k_final(float* __restrict__ out) {
    __shared__ float sums[110];
    int t = threadIdx.x;                 // 1024
    int w = t >> 5, lane = t & 31;
    for (int v = w; v < 110; v += 32) {
        float acc = 0.f;
        for (int tile = lane; tile < 1024; tile += 32)
            acc += g_part[tile * 110 + v];
        acc = wred(acc);
        if (!lane) sums[v] = acc;
    }
    __syncthreads();
    if (t == 0) {
        float loss = 0.f;
        for (int m = 0; m < 22; m++) {
            float ad  = sums[m * 5 + 0];
            float a01 = sums[m * 5 + 1];
            float b01 = sums[m * 5 + 2];
            float cd  = sums[m * 5 + 3];
            float c01 = sums[m * 5 + 4];
            loss += 0.5f * ad * ad + 2.f * a01 * a01
                  + 2.f * b01 * b01
                  + 0.5f * cd * cd + 2.f * c01 * c01;
        }
        out[0] = loss;
    }
}

extern "C" void kernel_launch(void* const* d_in, const int* in_sizes, int n_in,
                              void* d_out, int out_size) {
    const float* theta = (const float*)d_in[0];
    (void)in_sizes; (void)n_in; (void)out_size;
    k_prep<<<1, 1024>>>(theta);
    k_genA<<<1024, 512>>>();
    k_passB<<<1024, 512>>>();
    k_reduce<<<1024, 256>>>();
    k_final<<<1, 1024>>>((float*)d_out);
}

// round 9
// speedup vs baseline: 2.5616x; 1.0898x over previous
#include <cuda_runtime.h>

#define NQ 22
#define DIM (1u << 22)

// ---------------- device scratch (static: no allocation) ----------------
__device__ float g_psi0[DIM];
__device__ float g_psi1[DIM];
__device__ float g_cs1[NQ][2];
__device__ float g_Thi[2048];
__device__ float g_Tlo[2][2048];
__device__ float g_part[1024 * 110];

__device__ __forceinline__ float wred(float v) {
    #pragma unroll
    for (int o = 16; o; o >>= 1) v += __shfl_xor_sync(0xffffffffu, v, o);
    return v;
}
__device__ __forceinline__ float sgnx(float v, unsigned sb) {
    return __uint_as_float(__float_as_uint(v) ^ sb);
}
__device__ __forceinline__ float sf8(const float* y) {
    return ((y[0]-y[1]) - (y[2]-y[3])) - ((y[4]-y[5]) - (y[6]-y[7]));
}
__device__ __forceinline__ float sf4(const float* y) {
    return (y[0]-y[1]) - (y[2]-y[3]);
}

// ---------------- kernel 1: angles + product tables ----------------
__global__ void k_prep(const float* __restrict__ theta) {
    __shared__ float cs0[NQ][2];
    int t = threadIdx.x;
    if (t < NQ) {
        float h0 = 0.5f * theta[t];
        cs0[t][0] = cosf(h0);
        cs0[t][1] = sinf(h0);
        float h1 = 0.5f * theta[NQ + t];
        g_cs1[t][0] = cosf(h1);
        g_cs1[t][1] = sinf(h1);
    }
    __syncthreads();
    for (int v = t; v < 2048; v += blockDim.x) {
        float ph = 1.f;
        #pragma unroll
        for (int k = 0; k < 11; k++) {
            int q = 10 - k;
            int bit = (v >> k) & 1;
            ph *= cs0[q][bit];
        }
        g_Thi[v] = ph;
        float p0 = 1.f, p1 = 1.f;
        #pragma unroll
        for (int k = 0; k < 11; k++) {
            int q = 21 - k;
            int bit = (v >> k) & 1;
            float f = cs0[q][bit];
            p0 *= f;
            float f1 = (q == 21) ? (bit ? cs0[21][0] : -cs0[21][1]) : f;
            p1 *= f1;
        }
        g_Tlo[0][v] = p0;
        g_Tlo[1][v] = p1;
    }
}

// ---------------- kernel 2: state gen + layer-2 RY on bits 12..0 ----------------
__global__ void __launch_bounds__(512) k_genA() {
    __shared__ float s[8192];
    int bx = blockIdx.x;
    int st = bx >> 9;
    unsigned base = (unsigned)(bx & 511) << 13;
    int t = threadIdx.x;
    int lane = t & 31;

    // stage product tables into smem, XOR-swizzled (2-way worst-case conflicts)
    {
        const float* __restrict__ L = g_Tlo[st];
        for (int v = t; v < 2048; v += 512) {
            unsigned sw = (unsigned)v ^ (((unsigned)v >> 5) & 31u);
            s[sw] = g_Thi[v];
            s[2048 + sw] = L[v];
        }
    }
    __syncthreads();

    float r[16];
    #pragma unroll
    for (int i = 0; i < 16; i++) {
        unsigned y = base + (unsigned)(t * 16 + i);
        unsigned x = (y ^ (y >> 1)) ^ ((y & 1u) * 0x300000u);
        unsigned hi = x >> 11, lo = x & 2047u;
        r[i] = s[hi ^ ((hi >> 5) & 31u)] * s[2048 + (lo ^ ((lo >> 5) & 31u))];
    }

    // in-register stages: element bit br (0..3) -> qubit 21-br
    #pragma unroll
    for (int br = 0; br < 4; br++) {
        int q = 21 - br;
        float c = g_cs1[q][0], sn = g_cs1[q][1];
        #pragma unroll
        for (int i0 = 0; i0 < 16; i0++) if (!(i0 & (1 << br))) {
            int i1 = i0 | (1 << br);
            float a0 = r[i0], a1 = r[i1];
            r[i0] = c * a0 - sn * a1;
            r[i1] = sn * a0 + c * a1;
        }
    }
    // shuffle stages: element bit 4+lb -> qubit 17-lb
    #pragma unroll
    for (int lb = 0; lb < 5; lb++) {
        int q = 17 - lb;
        float c = g_cs1[q][0], sn = g_cs1[q][1];
        float ss = (lane & (1 << lb)) ? sn : -sn;
        #pragma unroll
        for (int i = 0; i < 16; i++) {
            float p = __shfl_xor_sync(0xffffffffu, r[i], 1 << lb);
            r[i] = fmaf(ss, p, c * r[i]);
        }
    }
    __syncthreads();   // tables no longer needed

    // swizzled exchange: rotate bits 9..12 into the register index
    #pragma unroll
    for (int i = 0; i < 16; i++) {
        unsigned o = (unsigned)(t * 16 + i);
        s[o ^ ((o >> 5) & 31u)] = r[i];
    }
    __syncthreads();
    #pragma unroll
    for (int j = 0; j < 16; j++) {
        unsigned o = ((unsigned)j << 9) | (unsigned)t;
        r[j] = s[o ^ ((o >> 5) & 31u)];
    }
    // in-register stages: element bit 9+bj -> qubit 12-bj
    #pragma unroll
    for (int bj = 0; bj < 4; bj++) {
        int q = 12 - bj;
        float c = g_cs1[q][0], sn = g_cs1[q][1];
        #pragma unroll
        for (int j0 = 0; j0 < 16; j0++) if (!(j0 & (1 << bj))) {
            int j1 = j0 | (1 << bj);
            float a0 = r[j0], a1 = r[j1];
            r[j0] = c * a0 - sn * a1;
            r[j1] = sn * a0 + c * a1;
        }
    }
    float* __restrict__ g = st ? g_psi1 : g_psi0;
    #pragma unroll
    for (int j = 0; j < 16; j++)
        g[base + ((unsigned)j << 9) + (unsigned)t] = r[j];
}

// ---------------- kernel 3: layer-2 RY on bits 13..21, register-blocked ----------------
__global__ void __launch_bounds__(512) k_passB() {
    __shared__ float s[512 * 17];
    int bx = blockIdx.x;
    int st = bx >> 9;
    unsigned mid = (unsigned)(bx & 511) << 4;
    float* __restrict__ g = st ? g_psi1 : g_psi0;
    int t = threadIdx.x;
    int lane = t & 31, w = t >> 5;   // w = 0..15

    const float4* G4 = (const float4*)g;
    for (int v = t; v < 2048; v += 512) {
        int hi = v >> 2, q = v & 3;
        float4 d = G4[((unsigned)hi << 11) + (mid >> 2) + (unsigned)q];
        int sb = hi * 17 + q * 4;
        s[sb + 0] = d.x; s[sb + 1] = d.y; s[sb + 2] = d.z; s[sb + 3] = d.w;
    }
    __syncthreads();

    float r[16];
    #pragma unroll
    for (int j = 0; j < 16; j++)
        r[j] = s[((j << 5) | lane) * 17 + w];

    #pragma unroll
    for (int lb = 0; lb < 5; lb++) {
        int q = 8 - lb;
        float c = g_cs1[q][0], sn = g_cs1[q][1];
        float ss = (lane & (1 << lb)) ? sn : -sn;
        #pragma unroll
        for (int j = 0; j < 16; j++) {
            float p = __shfl_xor_sync(0xffffffffu, r[j], 1 << lb);
            r[j] = fmaf(ss, p, c * r[j]);
        }
    }
    #pragma unroll
    for (int bj = 0; bj < 4; bj++) {
        int q = 3 - bj;
        float c = g_cs1[q][0], sn = g_cs1[q][1];
        #pragma unroll
        for (int j0 = 0; j0 < 16; j0++) if (!(j0 & (1 << bj))) {
            int j1 = j0 | (1 << bj);
            float a0 = r[j0], a1 = r[j1];
            r[j0] = c * a0 - sn * a1;
            r[j1] = sn * a0 + c * a1;
        }
    }
    #pragma unroll
    for (int j = 0; j < 16; j++)
        s[((j << 5) | lane) * 17 + w] = r[j];
    __syncthreads();

    float4* GW4 = (float4*)g;
    for (int v = t; v < 2048; v += 512) {
        int hi = v >> 2, q = v & 3;
        int sb = hi * 17 + q * 4;
        float4 d = make_float4(s[sb + 0], s[sb + 1], s[sb + 2], s[sb + 3]);
        GW4[((unsigned)hi << 11) + (mid >> 2) + (unsigned)q] = d;
    }
}

// ---------------- kernel 4: register-blocked Pauli reductions ----------------
// Slot layout (renumbered for group-ordered tree reduction):
//   0 Se, 1 Sf ; 2+k Ze_k, 14+k Zf_k (k=0..11)
//   m20:26..28  m19:29..31            (group 0 = slots 0..31)
//   m18:32..34  m17..13:35+3*(17-m)  m12..10:50+3*(12-m)  m0:59..62
//                                      (group 1 = slots 32..63)
//   m1..9:64+3*(m-1) (ad,U,V)  m21:91..94   (group 2 = slots 64..95)
__global__ void __launch_bounds__(256) k_reduce() {
    __shared__ float s0[4096];
    __shared__ float s1[4096];
    __shared__ float sacc[8][96];
    unsigned tile = blockIdx.x;
    unsigned base = tile << 12;
    int t = threadIdx.x, w = t >> 5, lane = t & 31;
    int c = t;

    float acc[96];
    #pragma unroll
    for (int k = 0; k < 96; k++) acc[k] = 0.f;

    float r0[16], r1[16];
    {
        const float4* G0 = (const float4*)(g_psi0 + base);
        const float4* G1 = (const float4*)(g_psi1 + base);
        float4* S0 = (float4*)s0;
        float4* S1 = (float4*)s1;
        #pragma unroll
        for (int q = 0; q < 4; q++) {
            float4 a = G0[c * 4 + q]; S0[c * 4 + q] = a;
            r0[q*4+0] = a.x; r0[q*4+1] = a.y; r0[q*4+2] = a.z; r0[q*4+3] = a.w;
            float4 b = G1[c * 4 + q]; S1[c * 4 + q] = b;
            r1[q*4+0] = b.x; r1[q*4+1] = b.y; r1[q*4+2] = b.z; r1[q*4+3] = b.w;
        }
    }
    unsigned H = ((unsigned)(__popc(t & 0xFF) & 1)) << 31;

    // batched tree reduce of 32 consecutive slots; lane l ends with slot base+l
    #define TREE32(BS) { \
        _Pragma("unroll") \
        for (int off = 16; off >= 1; off >>= 1) { \
            _Pragma("unroll") \
            for (int k = 0; k < off; k++) { \
                float send = (lane & off) ? acc[(BS)+k] : acc[(BS)+k+off]; \
                float recv = __shfl_xor_sync(0xffffffffu, send, off); \
                acc[(BS)+k] = ((lane & off) ? acc[(BS)+k+off] : acc[(BS)+k]) + recv; \
            } \
        } \
        sacc[w][(BS) + lane] = acc[(BS)]; \
    }

    #define ZFOLD(EXPR, IDXBASE, TOTIDX) { \
        float x[16]; \
        _Pragma("unroll") for (int i = 0; i < 16; i++) x[i] = (EXPR); \
        float s1a[8], d0[8]; \
        _Pragma("unroll") for (int j = 0; j < 8; j++) { \
            s1a[j] = x[2*j] + x[2*j+1]; d0[j] = x[2*j] - x[2*j+1]; } \
        float D0 = sf8(d0), D1 = sf8(s1a); \
        float s2[4]; \
        _Pragma("unroll") for (int j = 0; j < 4; j++) s2[j] = s1a[2*j] + s1a[2*j+1]; \
        float D2 = sf4(s2); \
        float s3a = s2[0] + s2[1], s3b = s2[2] + s2[3]; \
        float D3 = s3a - s3b, T = s3a + s3b; \
        acc[(IDXBASE)+0] = sgnx(D0, H); \
        acc[(IDXBASE)+1] = sgnx(D1, H); \
        acc[(IDXBASE)+2] = sgnx(D2, H); \
        acc[(IDXBASE)+3] = sgnx(D3, H); \
        _Pragma("unroll") for (int k = 4; k < 12; k++) { \
            unsigned hk = ((unsigned)(__popc((unsigned)t >> (k-4)) & 1)) << 31; \
            acc[(IDXBASE)+k] = sgnx(T, hk); } \
        acc[TOTIDX] = T; }

    ZFOLD(r0[i]*r0[i] - r1[i]*r1[i], 2, 0)
    ZFOLD(r0[i]*r1[i], 14, 1)
    #undef ZFOLD

    #define INREG(SLOT, MSK, PB) { \
        float ad = 0.f, us = 0.f, wr = 0.f; \
        _Pragma("unroll") for (int i = 0; i < 16; i++) { \
            float p0 = r0[i ^ (MSK)], p1 = r1[i ^ (MSK)]; \
            ad += r0[i]*p0 - r1[i]*p1; \
            float u = r0[i]*p1; us += u; \
            if (__popc(i >> (PB)) & 1) wr -= u; else wr += u; } \
        acc[(SLOT)+0] = ad; acc[(SLOT)+1] = us; acc[(SLOT)+2] = sgnx(wr, H); }
    INREG(26, 3, 1)    // m=20
    INREG(29, 6, 2)    // m=19
    TREE32(0)          // group 0 complete
    INREG(32, 12, 3)   // m=18
    #undef INREG

    #define SHFM(SLOT, MM, LX, IX) { \
        float ad = 0.f, us = 0.f; \
        _Pragma("unroll") for (int i = 0; i < 16; i++) { \
            float p0 = __shfl_xor_sync(0xffffffffu, r0[i ^ (IX)], (LX)); \
            float p1 = __shfl_xor_sync(0xffffffffu, r1[i ^ (IX)], (LX)); \
            ad += r0[i]*p0 - r1[i]*p1; us += r0[i]*p1; } \
        unsigned hs = ((unsigned)(__popc((unsigned)t >> (21-(MM)-4)) & 1)) << 31; \
        acc[(SLOT)+0] = ad; acc[(SLOT)+1] = us; acc[(SLOT)+2] = sgnx(us, hs); }
    SHFM(35, 17, 1, 8)
    SHFM(38, 16, 3, 0)
    SHFM(41, 15, 6, 0)
    SHFM(44, 14, 12, 0)
    SHFM(47, 13, 24, 0)
    #undef SHFM

    __syncthreads();

    #define SMEMM(SLOT, MM, CX) { \
        float ad = 0.f, us = 0.f; \
        const float4* S04 = (const float4*)s0; \
        const float4* S14 = (const float4*)s1; \
        _Pragma("unroll") for (int q = 0; q < 4; q++) { \
            float4 a = S04[(c ^ (CX)) * 4 + q], b = S14[(c ^ (CX)) * 4 + q]; \
            float pa[4] = {a.x, a.y, a.z, a.w}; \
            float pb[4] = {b.x, b.y, b.z, b.w}; \
            _Pragma("unroll") for (int z = 0; z < 4; z++) { \
                int i = q*4 + z; \
                ad += r0[i]*pa[z] - r1[i]*pb[z]; us += r0[i]*pb[z]; } } \
        unsigned hs = ((unsigned)(__popc((unsigned)t >> (21-(MM)-4)) & 1)) << 31; \
        acc[(SLOT)+0] = ad; acc[(SLOT)+1] = us; acc[(SLOT)+2] = sgnx(us, hs); }
    SMEMM(50, 12, 0x30)
    SMEMM(53, 11, 0x60)
    SMEMM(56, 10, 0xC0)
    #undef SMEMM

    #define CROSSM(SLOT, DH, CH, SWAP, DOW, CONDBIT) \
    if (!(base & (CONDBIT))) { \
        float ad = 0.f, U = 0.f, V = 0.f, wr = 0.f; \
        const float4* P0 = (const float4*)(g_psi0 + (base ^ (DH))); \
        const float4* P1 = (const float4*)(g_psi1 + (base ^ (DH))); \
        _Pragma("unroll") for (int q = 0; q < 4; q++) { \
            float4 a = P0[(c ^ (CH)) * 4 + q], b = P1[(c ^ (CH)) * 4 + q]; \
            float pa[4] = {a.x, a.y, a.z, a.w}; \
            float pb[4] = {b.x, b.y, b.z, b.w}; \
            _Pragma("unroll") for (int z = 0; z < 4; z++) { \
                int i = q*4 + z; int zz = (SWAP) ? (z ^ 1) : z; \
                float p0 = pa[zz], p1 = pb[zz]; \
                ad += r0[i]*p0 - r1[i]*p1; \
                float u = r0[i]*p1, vv = p0*r1[i]; \
                U += u; V += vv; \
                if (DOW) { if (__popc(i) & 1) wr -= (u - vv); else wr += (u - vv); } } } \
        acc[(SLOT)+0] = ad; acc[(SLOT)+1] = U; acc[(SLOT)+2] = V; \
        if (DOW) acc[(SLOT)+3] = sgnx(wr, H); }

    CROSSM(59, 0x300000u, 0, 0, 1, 0x200000u)      // m=0
    TREE32(32)                                     // group 1 complete
    CROSSM(64, (3u<<19), 0, 0, 0, (1u<<20))        // m=1
    CROSSM(67, (3u<<18), 0, 0, 0, (1u<<19))        // m=2
    CROSSM(70, (3u<<17), 0, 0, 0, (1u<<18))        // m=3
    CROSSM(73, (3u<<16), 0, 0, 0, (1u<<17))        // m=4
    CROSSM(76, (3u<<15), 0, 0, 0, (1u<<16))        // m=5
    CROSSM(79, (3u<<14), 0, 0, 0, (1u<<15))        // m=6
    CROSSM(82, (3u<<13), 0, 0, 0, (1u<<14))        // m=7
    CROSSM(85, (3u<<12), 0, 0, 0, (1u<<13))        // m=8
    CROSSM(88, 0x1000u, 0x80, 0, 0, (1u<<12))      // m=9
    CROSSM(91, 0x300000u, 0, 1, 1, 0x200000u)      // m=21
    TREE32(64)                                     // group 2 complete
    #undef CROSSM
    #undef TREE32

    __syncthreads();

    if (t < 96) {
        float a = 0.f;
        #pragma unroll
        for (int r = 0; r < 8; r++) a += sacc[r][t];
        sacc[0][t] = a;
    }
    __syncthreads();

    if (t < 22) {
        int m = t;
        const float* S = sacc[0];
        unsigned Pm = (m == 0) ? 0x1FFFFFu : (((1u << (m + 1)) - 1u) << (21 - m));
        float s = (__popc(base & Pm) & 1) ? -1.f : 1.f;
        float cd, c01, ad, a01, b01;
        if (m >= 10 && m <= 20) {
            int k = 21 - m;
            cd = s * S[2 + k]; c01 = s * S[14 + k];
            int b = (m >= 18) ? (26 + 3 * (20 - m))
                  : (m >= 13) ? (35 + 3 * (17 - m))
                              : (50 + 3 * (12 - m));
            ad = S[b]; a01 = S[b + 1]; b01 = -s * S[b + 2];
        } else if (m >= 1 && m <= 9) {
            cd = s * S[0]; c01 = s * S[1];
            if (base & (1u << (21 - m))) {
                ad = 0.f; a01 = 0.f; b01 = 0.f;
            } else {
                int sl = 64 + 3 * (m - 1);
                float U = S[sl + 1], V = S[sl + 2];
                ad = 2.f * S[sl];
                a01 = U + V;
                b01 = -s * (U - V);
            }
        } else if (m == 0) {
            cd = s * S[2]; c01 = s * S[14];
            if (base & 0x200000u) { ad = 0.f; a01 = 0.f; b01 = 0.f; }
            else {
                ad = 2.f * S[59];
                a01 = S[60] + S[61];
                b01 = -s * S[62];
            }
        } else { // m == 21
            cd = s * S[2]; c01 = s * S[14];
            if (base & 0x200000u) { ad = 0.f; a01 = 0.f; b01 = 0.f; }
            else {
                ad = 2.f * S[91];
                a01 = S[92] + S[93];
                b01 = -s * S[94];
            }
        }
        float* pp = &g_part[tile * 110 + (unsigned)m * 5];
        pp[0] = ad; pp[1] = a01; pp[2] = b01; pp[3] = cd; pp[4] = c01;
    }
}

// ---------------- kernel 5: final combine ----------------
__global__ void k_final(float* __restrict__ out) {
    __shared__ float sums[110];
    int t = threadIdx.x;                 // 1024
    int w = t >> 5, lane = t & 31;
    for (int v = w; v < 110; v += 32) {
        float acc = 0.f;
        for (int tile = lane; tile < 1024; tile += 32)
            acc += g_part[tile * 110 + v];
        acc = wred(acc);
        if (!lane) sums[v] = acc;
    }
    __syncthreads();
    if (t == 0) {
        float loss = 0.f;
        for (int m = 0; m < 22; m++) {
            float ad  = sums[m * 5 + 0];
            float a01 = sums[m * 5 + 1];
            float b01 = sums[m * 5 + 2];
            float cd  = sums[m * 5 + 3];
            float c01 = sums[m * 5 + 4];
            loss += 0.5f * ad * ad + 2.f * a01 * a01
                  + 2.f * b01 * b01
                  + 0.5f * cd * cd + 2.f * c01 * c01;
        }
        out[0] = loss;
    }
}

extern "C" void kernel_launch(void* const* d_in, const int* in_sizes, int n_in,
                              void* d_out, int out_size) {
    const float* theta = (const float*)d_in[0];
    (void)in_sizes; (void)n_in; (void)out_size;
    k_prep<<<1, 1024>>>(theta);
    k_genA<<<1024, 512>>>();
    k_passB<<<1024, 512>>>();
    k_reduce<<<1024, 256>>>();
    k_final<<<1, 1024>>>((float*)d_out);
}

// round 10
// speedup vs baseline: 2.5838x; 1.0087x over previous
#include <cuda_runtime.h>

#define NQ 22
#define DIM (1u << 22)

// ---------------- device scratch (static: no allocation) ----------------
__device__ float g_psi0[DIM];
__device__ float g_psi1[DIM];
__device__ float g_part[1024 * 110];

__device__ __forceinline__ float wred(float v) {
    #pragma unroll
    for (int o = 16; o; o >>= 1) v += __shfl_xor_sync(0xffffffffu, v, o);
    return v;
}
__device__ __forceinline__ float sgnx(float v, unsigned sb) {
    return __uint_as_float(__float_as_uint(v) ^ sb);
}
__device__ __forceinline__ float sf8(const float* y) {
    return ((y[0]-y[1]) - (y[2]-y[3])) - ((y[4]-y[5]) - (y[6]-y[7]));
}
__device__ __forceinline__ float sf4(const float* y) {
    return (y[0]-y[1]) - (y[2]-y[3]);
}

// ---------------- kernel 1: state gen + layer-2 RY on bits 12..0 ----------------
// Tables computed in-block from theta (k_prep folded in).
__global__ void __launch_bounds__(512, 2) k_genA(const float* __restrict__ theta) {
    __shared__ float s[8192];
    __shared__ float cs0s[NQ][2];
    __shared__ float cs1s[NQ][2];
    int bx = blockIdx.x;
    int st = bx >> 9;
    unsigned base = (unsigned)(bx & 511) << 13;
    int t = threadIdx.x;
    int lane = t & 31;

    if (t < NQ) {
        float h0 = 0.5f * theta[t];
        cs0s[t][0] = cosf(h0); cs0s[t][1] = sinf(h0);
        float h1 = 0.5f * theta[NQ + t];
        cs1s[t][0] = cosf(h1); cs1s[t][1] = sinf(h1);
    }
    __syncthreads();

    // build swizzled product tables in smem
    #pragma unroll
    for (int rep = 0; rep < 4; rep++) {
        int v = t + rep * 512;
        float ph = 1.f;
        #pragma unroll
        for (int k = 0; k < 11; k++)
            ph *= cs0s[10 - k][(v >> k) & 1];
        float pl = 1.f;
        #pragma unroll
        for (int k = 1; k < 11; k++)
            pl *= cs0s[21 - k][(v >> k) & 1];
        int b0 = v & 1;
        float f21 = st ? (b0 ? cs0s[21][0] : -cs0s[21][1]) : cs0s[21][b0];
        unsigned sw = (unsigned)v ^ (((unsigned)v >> 5) & 31u);
        s[sw] = ph;
        s[2048 + sw] = pl * f21;
    }
    __syncthreads();

    float r[16];
    #pragma unroll
    for (int i = 0; i < 16; i++) {
        unsigned y = base + (unsigned)(t * 16 + i);
        unsigned x = (y ^ (y >> 1)) ^ ((y & 1u) * 0x300000u);
        unsigned hi = x >> 11, lo = x & 2047u;
        r[i] = s[hi ^ ((hi >> 5) & 31u)] * s[2048 + (lo ^ ((lo >> 5) & 31u))];
    }

    // in-register stages: element bit br (0..3) -> qubit 21-br
    #pragma unroll
    for (int br = 0; br < 4; br++) {
        int q = 21 - br;
        float c = cs1s[q][0], sn = cs1s[q][1];
        #pragma unroll
        for (int i0 = 0; i0 < 16; i0++) if (!(i0 & (1 << br))) {
            int i1 = i0 | (1 << br);
            float a0 = r[i0], a1 = r[i1];
            r[i0] = c * a0 - sn * a1;
            r[i1] = sn * a0 + c * a1;
        }
    }
    // shuffle stages: element bit 4+lb -> qubit 17-lb
    #pragma unroll
    for (int lb = 0; lb < 5; lb++) {
        int q = 17 - lb;
        float c = cs1s[q][0], sn = cs1s[q][1];
        float ss = (lane & (1 << lb)) ? sn : -sn;
        #pragma unroll
        for (int i = 0; i < 16; i++) {
            float p = __shfl_xor_sync(0xffffffffu, r[i], 1 << lb);
            r[i] = fmaf(ss, p, c * r[i]);
        }
    }
    __syncthreads();   // tables no longer needed

    // swizzled exchange: rotate bits 9..12 into the register index
    #pragma unroll
    for (int i = 0; i < 16; i++) {
        unsigned o = (unsigned)(t * 16 + i);
        s[o ^ ((o >> 5) & 31u)] = r[i];
    }
    __syncthreads();
    #pragma unroll
    for (int j = 0; j < 16; j++) {
        unsigned o = ((unsigned)j << 9) | (unsigned)t;
        r[j] = s[o ^ ((o >> 5) & 31u)];
    }
    // in-register stages: element bit 9+bj -> qubit 12-bj
    #pragma unroll
    for (int bj = 0; bj < 4; bj++) {
        int q = 12 - bj;
        float c = cs1s[q][0], sn = cs1s[q][1];
        #pragma unroll
        for (int j0 = 0; j0 < 16; j0++) if (!(j0 & (1 << bj))) {
            int j1 = j0 | (1 << bj);
            float a0 = r[j0], a1 = r[j1];
            r[j0] = c * a0 - sn * a1;
            r[j1] = sn * a0 + c * a1;
        }
    }
    float* __restrict__ g = st ? g_psi1 : g_psi0;
    #pragma unroll
    for (int j = 0; j < 16; j++)
        g[base + ((unsigned)j << 9) + (unsigned)t] = r[j];
}

// ---------------- kernel 2: layer-2 RY on bits 13..21, register-blocked ----------------
__global__ void __launch_bounds__(512, 2) k_passB(const float* __restrict__ theta) {
    __shared__ float s[512 * 17];
    __shared__ float cs1s[NQ][2];
    int bx = blockIdx.x;
    int st = bx >> 9;
    unsigned mid = (unsigned)(bx & 511) << 4;
    float* __restrict__ g = st ? g_psi1 : g_psi0;
    int t = threadIdx.x;
    int lane = t & 31, w = t >> 5;   // w = 0..15

    if (t < NQ) {
        float h1 = 0.5f * theta[NQ + t];
        cs1s[t][0] = cosf(h1); cs1s[t][1] = sinf(h1);
    }

    const float4* G4 = (const float4*)g;
    for (int v = t; v < 2048; v += 512) {
        int hi = v >> 2, q = v & 3;
        float4 d = G4[((unsigned)hi << 11) + (mid >> 2) + (unsigned)q];
        int sb = hi * 17 + q * 4;
        s[sb + 0] = d.x; s[sb + 1] = d.y; s[sb + 2] = d.z; s[sb + 3] = d.w;
    }
    __syncthreads();

    float r[16];
    #pragma unroll
    for (int j = 0; j < 16; j++)
        r[j] = s[((j << 5) | lane) * 17 + w];

    #pragma unroll
    for (int lb = 0; lb < 5; lb++) {
        int q = 8 - lb;
        float c = cs1s[q][0], sn = cs1s[q][1];
        float ss = (lane & (1 << lb)) ? sn : -sn;
        #pragma unroll
        for (int j = 0; j < 16; j++) {
            float p = __shfl_xor_sync(0xffffffffu, r[j], 1 << lb);
            r[j] = fmaf(ss, p, c * r[j]);
        }
    }
    #pragma unroll
    for (int bj = 0; bj < 4; bj++) {
        int q = 3 - bj;
        float c = cs1s[q][0], sn = cs1s[q][1];
        #pragma unroll
        for (int j0 = 0; j0 < 16; j0++) if (!(j0 & (1 << bj))) {
            int j1 = j0 | (1 << bj);
            float a0 = r[j0], a1 = r[j1];
            r[j0] = c * a0 - sn * a1;
            r[j1] = sn * a0 + c * a1;
        }
    }
    #pragma unroll
    for (int j = 0; j < 16; j++)
        s[((j << 5) | lane) * 17 + w] = r[j];
    __syncthreads();

    float4* GW4 = (float4*)g;
    for (int v = t; v < 2048; v += 512) {
        int hi = v >> 2, q = v & 3;
        int sb = hi * 17 + q * 4;
        float4 d = make_float4(s[sb + 0], s[sb + 1], s[sb + 2], s[sb + 3]);
        GW4[((unsigned)hi << 11) + (mid >> 2) + (unsigned)q] = d;
    }
}

// ---------------- kernel 3: register-blocked Pauli reductions ----------------
// Slot layout (group-ordered tree reduction):
//   0 Se, 1 Sf ; 2+k Ze_k, 14+k Zf_k (k=0..11)
//   m20:26..28  m19:29..31            (group 0 = slots 0..31)
//   m18:32..34  m17..13:35+3*(17-m)  m12..10:50+3*(12-m)  m0:59..62
//                                      (group 1 = slots 32..63)
//   m1..9:64+3*(m-1) (ad,U,V)  m21:91..94   (group 2 = slots 64..95)
__global__ void __launch_bounds__(256, 3) k_reduce() {
    __shared__ float s0[4096];
    __shared__ float s1[4096];
    __shared__ float sacc[8][96];
    unsigned tile = blockIdx.x;
    unsigned base = tile << 12;
    int t = threadIdx.x, w = t >> 5, lane = t & 31;
    int c = t;

    float acc[96];
    #pragma unroll
    for (int k = 0; k < 96; k++) acc[k] = 0.f;

    float r0[16], r1[16];
    {
        const float4* G0 = (const float4*)(g_psi0 + base);
        const float4* G1 = (const float4*)(g_psi1 + base);
        float4* S0 = (float4*)s0;
        float4* S1 = (float4*)s1;
        #pragma unroll
        for (int q = 0; q < 4; q++) {
            float4 a = G0[c * 4 + q]; S0[c * 4 + q] = a;
            r0[q*4+0] = a.x; r0[q*4+1] = a.y; r0[q*4+2] = a.z; r0[q*4+3] = a.w;
            float4 b = G1[c * 4 + q]; S1[c * 4 + q] = b;
            r1[q*4+0] = b.x; r1[q*4+1] = b.y; r1[q*4+2] = b.z; r1[q*4+3] = b.w;
        }
    }
    unsigned H = ((unsigned)(__popc(t & 0xFF) & 1)) << 31;

    // batched tree reduce of 32 consecutive slots; lane l ends with slot base+l
    #define TREE32(BS) { \
        _Pragma("unroll") \
        for (int off = 16; off >= 1; off >>= 1) { \
            _Pragma("unroll") \
            for (int k = 0; k < off; k++) { \
                float send = (lane & off) ? acc[(BS)+k] : acc[(BS)+k+off]; \
                float recv = __shfl_xor_sync(0xffffffffu, send, off); \
                acc[(BS)+k] = ((lane & off) ? acc[(BS)+k+off] : acc[(BS)+k]) + recv; \
            } \
        } \
        sacc[w][(BS) + lane] = acc[(BS)]; \
    }

    #define ZFOLD(EXPR, IDXBASE, TOTIDX) { \
        float x[16]; \
        _Pragma("unroll") for (int i = 0; i < 16; i++) x[i] = (EXPR); \
        float s1a[8], d0[8]; \
        _Pragma("unroll") for (int j = 0; j < 8; j++) { \
            s1a[j] = x[2*j] + x[2*j+1]; d0[j] = x[2*j] - x[2*j+1]; } \
        float D0 = sf8(d0), D1 = sf8(s1a); \
        float s2[4]; \
        _Pragma("unroll") for (int j = 0; j < 4; j++) s2[j] = s1a[2*j] + s1a[2*j+1]; \
        float D2 = sf4(s2); \
        float s3a = s2[0] + s2[1], s3b = s2[2] + s2[3]; \
        float D3 = s3a - s3b, T = s3a + s3b; \
        acc[(IDXBASE)+0] = sgnx(D0, H); \
        acc[(IDXBASE)+1] = sgnx(D1, H); \
        acc[(IDXBASE)+2] = sgnx(D2, H); \
        acc[(IDXBASE)+3] = sgnx(D3, H); \
        _Pragma("unroll") for (int k = 4; k < 12; k++) { \
            unsigned hk = ((unsigned)(__popc((unsigned)t >> (k-4)) & 1)) << 31; \
            acc[(IDXBASE)+k] = sgnx(T, hk); } \
        acc[TOTIDX] = T; }

    ZFOLD(r0[i]*r0[i] - r1[i]*r1[i], 2, 0)
    ZFOLD(r0[i]*r1[i], 14, 1)
    #undef ZFOLD

    #define INREG(SLOT, MSK, PB) { \
        float ad = 0.f, us = 0.f, wr = 0.f; \
        _Pragma("unroll") for (int i = 0; i < 16; i++) { \
            float p0 = r0[i ^ (MSK)], p1 = r1[i ^ (MSK)]; \
            ad += r0[i]*p0 - r1[i]*p1; \
            float u = r0[i]*p1; us += u; \
            if (__popc(i >> (PB)) & 1) wr -= u; else wr += u; } \
        acc[(SLOT)+0] = ad; acc[(SLOT)+1] = us; acc[(SLOT)+2] = sgnx(wr, H); }
    INREG(26, 3, 1)    // m=20
    INREG(29, 6, 2)    // m=19
    TREE32(0)          // group 0 complete
    INREG(32, 12, 3)   // m=18
    #undef INREG

    #define SHFM(SLOT, MM, LX, IX) { \
        float ad = 0.f, us = 0.f; \
        _Pragma("unroll") for (int i = 0; i < 16; i++) { \
            float p0 = __shfl_xor_sync(0xffffffffu, r0[i ^ (IX)], (LX)); \
            float p1 = __shfl_xor_sync(0xffffffffu, r1[i ^ (IX)], (LX)); \
            ad += r0[i]*p0 - r1[i]*p1; us += r0[i]*p1; } \
        unsigned hs = ((unsigned)(__popc((unsigned)t >> (21-(MM)-4)) & 1)) << 31; \
        acc[(SLOT)+0] = ad; acc[(SLOT)+1] = us; acc[(SLOT)+2] = sgnx(us, hs); }
    SHFM(35, 17, 1, 8)
    SHFM(38, 16, 3, 0)
    SHFM(41, 15, 6, 0)
    SHFM(44, 14, 12, 0)
    SHFM(47, 13, 24, 0)
    #undef SHFM

    __syncthreads();

    #define SMEMM(SLOT, MM, CX) { \
        float ad = 0.f, us = 0.f; \
        const float4* S04 = (const float4*)s0; \
        const float4* S14 = (const float4*)s1; \
        _Pragma("unroll") for (int q = 0; q < 4; q++) { \
            float4 a = S04[(c ^ (CX)) * 4 + q], b = S14[(c ^ (CX)) * 4 + q]; \
            float pa[4] = {a.x, a.y, a.z, a.w}; \
            float pb[4] = {b.x, b.y, b.z, b.w}; \
            _Pragma("unroll") for (int z = 0; z < 4; z++) { \
                int i = q*4 + z; \
                ad += r0[i]*pa[z] - r1[i]*pb[z]; us += r0[i]*pb[z]; } } \
        unsigned hs = ((unsigned)(__popc((unsigned)t >> (21-(MM)-4)) & 1)) << 31; \
        acc[(SLOT)+0] = ad; acc[(SLOT)+1] = us; acc[(SLOT)+2] = sgnx(us, hs); }
    SMEMM(50, 12, 0x30)
    SMEMM(53, 11, 0x60)
    SMEMM(56, 10, 0xC0)
    #undef SMEMM

    #define CROSSM(SLOT, DH, CH, SWAP, DOW, CONDBIT) \
    if (!(base & (CONDBIT))) { \
        float ad = 0.f, U = 0.f, V = 0.f, wr = 0.f; \
        const float4* P0 = (const float4*)(g_psi0 + (base ^ (DH))); \
        const float4* P1 = (const float4*)(g_psi1 + (base ^ (DH))); \
        _Pragma("unroll") for (int q = 0; q < 4; q++) { \
            float4 a = P0[(c ^ (CH)) * 4 + q], b = P1[(c ^ (CH)) * 4 + q]; \
            float pa[4] = {a.x, a.y, a.z, a.w}; \
            float pb[4] = {b.x, b.y, b.z, b.w}; \
            _Pragma("unroll") for (int z = 0; z < 4; z++) { \
                int i = q*4 + z; int zz = (SWAP) ? (z ^ 1) : z; \
                float p0 = pa[zz], p1 = pb[zz]; \
                ad += r0[i]*p0 - r1[i]*p1; \
                float u = r0[i]*p1, vv = p0*r1[i]; \
                U += u; V += vv; \
                if (DOW) { if (__popc(i) & 1) wr -= (u - vv); else wr += (u - vv); } } } \
        acc[(SLOT)+0] = ad; acc[(SLOT)+1] = U; acc[(SLOT)+2] = V; \
        if (DOW) acc[(SLOT)+3] = sgnx(wr, H); }

    CROSSM(59, 0x300000u, 0, 0, 1, 0x200000u)      // m=0
    TREE32(32)                                     // group 1 complete
    CROSSM(64, (3u<<19), 0, 0, 0, (1u<<20))        // m=1
    CROSSM(67, (3u<<18), 0, 0, 0, (1u<<19))        // m=2
    CROSSM(70, (3u<<17), 0, 0, 0, (1u<<18))        // m=3
    CROSSM(73, (3u<<16), 0, 0, 0, (1u<<17))        // m=4
    CROSSM(76, (3u<<15), 0, 0, 0, (1u<<16))        // m=5
    CROSSM(79, (3u<<14), 0, 0, 0, (1u<<15))        // m=6
    CROSSM(82, (3u<<13), 0, 0, 0, (1u<<14))        // m=7
    CROSSM(85, (3u<<12), 0, 0, 0, (1u<<13))        // m=8
    CROSSM(88, 0x1000u, 0x80, 0, 0, (1u<<12))      // m=9
    CROSSM(91, 0x300000u, 0, 1, 1, 0x200000u)      // m=21
    TREE32(64)                                     // group 2 complete
    #undef CROSSM
    #undef TREE32

    __syncthreads();

    if (t < 96) {
        float a = 0.f;
        #pragma unroll
        for (int r = 0; r < 8; r++) a += sacc[r][t];
        sacc[0][t] = a;
    }
    __syncthreads();

    if (t < 22) {
        int m = t;
        const float* S = sacc[0];
        unsigned Pm = (m == 0) ? 0x1FFFFFu : (((1u << (m + 1)) - 1u) << (21 - m));
        float s = (__popc(base & Pm) & 1) ? -1.f : 1.f;
        float cd, c01, ad, a01, b01;
        if (m >= 10 && m <= 20) {
            int k = 21 - m;
            cd = s * S[2 + k]; c01 = s * S[14 + k];
            int b = (m >= 18) ? (26 + 3 * (20 - m))
                  : (m >= 13) ? (35 + 3 * (17 - m))
                              : (50 + 3 * (12 - m));
            ad = S[b]; a01 = S[b + 1]; b01 = -s * S[b + 2];
        } else if (m >= 1 && m <= 9) {
            cd = s * S[0]; c01 = s * S[1];
            if (base & (1u << (21 - m))) {
                ad = 0.f; a01 = 0.f; b01 = 0.f;
            } else {
                int sl = 64 + 3 * (m - 1);
                float U = S[sl + 1], V = S[sl + 2];
                ad = 2.f * S[sl];
                a01 = U + V;
                b01 = -s * (U - V);
            }
        } else if (m == 0) {
            cd = s * S[2]; c01 = s * S[14];
            if (base & 0x200000u) { ad = 0.f; a01 = 0.f; b01 = 0.f; }
            else {
                ad = 2.f * S[59];
                a01 = S[60] + S[61];
                b01 = -s * S[62];
            }
        } else { // m == 21
            cd = s * S[2]; c01 = s * S[14];
            if (base & 0x200000u) { ad = 0.f; a01 = 0.f; b01 = 0.f; }
            else {
                ad = 2.f * S[91];
                a01 = S[92] + S[93];
                b01 = -s * S[94];
            }
        }
        float* pp = &g_part[tile * 110 + (unsigned)m * 5];
        pp[0] = ad; pp[1] = a01; pp[2] = b01; pp[3] = cd; pp[4] = c01;
    }
}

// ---------------- kernel 4: final combine ----------------
__global__ void k_final(float* __restrict__ out) {
    __shared__ float sums[110];
    int t = threadIdx.x;                 // 1024
    int w = t >> 5, lane = t & 31;
    for (int v = w; v < 110; v += 32) {
        float acc = 0.f;
        for (int tile = lane; tile < 1024; tile += 32)
            acc += g_part[tile * 110 + v];
        acc = wred(acc);
        if (!lane) sums[v] = acc;
    }
    __syncthreads();
    if (t == 0) {
        float loss = 0.f;
        for (int m = 0; m < 22; m++) {
            float ad  = sums[m * 5 + 0];
            float a01 = sums[m * 5 + 1];
            float b01 = sums[m * 5 + 2];
            float cd  = sums[m * 5 + 3];
            float c01 = sums[m * 5 + 4];
            loss += 0.5f * ad * ad + 2.f * a01 * a01
                  + 2.f * b01 * b01
                  + 0.5f * cd * cd + 2.f * c01 * c01;
        }
        out[0] = loss;
    }
}

extern "C" void kernel_launch(void* const* d_in, const int* in_sizes, int n_in,
                              void* d_out, int out_size) {
    const float* theta = (const float*)d_in[0];
    (void)in_sizes; (void)n_in; (void)out_size;
    k_genA<<<1024, 512>>>(theta);
    k_passB<<<1024, 512>>>(theta);
    k_reduce<<<1024, 256>>>();
    k_final<<<1, 1024>>>((float*)d_out);
}

// round 11
// speedup vs baseline: 3.1063x; 1.2022x over previous
#include <cuda_runtime.h>

#define NQ 22
#define DIM (1u << 22)

// ---------------- device scratch (static: no allocation) ----------------
__device__ float g_psi0[DIM];
__device__ float g_psi1[DIM];
__device__ float g_sums[110];

__device__ __forceinline__ float wred(float v) {
    #pragma unroll
    for (int o = 16; o; o >>= 1) v += __shfl_xor_sync(0xffffffffu, v, o);
    return v;
}
__device__ __forceinline__ float sgnx(float v, unsigned sb) {
    return __uint_as_float(__float_as_uint(v) ^ sb);
}
__device__ __forceinline__ float sf8(const float* y) {
    return ((y[0]-y[1]) - (y[2]-y[3])) - ((y[4]-y[5]) - (y[6]-y[7]));
}
__device__ __forceinline__ float sf4(const float* y) {
    return (y[0]-y[1]) - (y[2]-y[3]);
}

// ---------------- kernel 1: state gen + layer-2 RY on bits 12..0 ----------------
__global__ void __launch_bounds__(512, 2) k_genA(const float* __restrict__ theta) {
    __shared__ float s[8192];
    __shared__ float cs0s[NQ][2];
    __shared__ float cs1s[NQ][2];
    int bx = blockIdx.x;
    int st = bx >> 9;
    unsigned base = (unsigned)(bx & 511) << 13;
    int t = threadIdx.x;
    int lane = t & 31;

    // block 0 zeroes the global accumulators for this launch (replay-safe:
    // kernel-boundary ordering puts this before any k_reduce atomic)
    if (bx == 0 && t < 110) g_sums[t] = 0.f;

    if (t < NQ) {
        float h0 = 0.5f * theta[t];
        cs0s[t][0] = cosf(h0); cs0s[t][1] = sinf(h0);
        float h1 = 0.5f * theta[NQ + t];
        cs1s[t][0] = cosf(h1); cs1s[t][1] = sinf(h1);
    }
    __syncthreads();

    // build swizzled product tables in smem
    #pragma unroll
    for (int rep = 0; rep < 4; rep++) {
        int v = t + rep * 512;
        float ph = 1.f;
        #pragma unroll
        for (int k = 0; k < 11; k++)
            ph *= cs0s[10 - k][(v >> k) & 1];
        float pl = 1.f;
        #pragma unroll
        for (int k = 1; k < 11; k++)
            pl *= cs0s[21 - k][(v >> k) & 1];
        int b0 = v & 1;
        float f21 = st ? (b0 ? cs0s[21][0] : -cs0s[21][1]) : cs0s[21][b0];
        unsigned sw = (unsigned)v ^ (((unsigned)v >> 5) & 31u);
        s[sw] = ph;
        s[2048 + sw] = pl * f21;
    }
    __syncthreads();

    float r[16];
    #pragma unroll
    for (int i = 0; i < 16; i++) {
        unsigned y = base + (unsigned)(t * 16 + i);
        unsigned x = (y ^ (y >> 1)) ^ ((y & 1u) * 0x300000u);
        unsigned hi = x >> 11, lo = x & 2047u;
        r[i] = s[hi ^ ((hi >> 5) & 31u)] * s[2048 + (lo ^ ((lo >> 5) & 31u))];
    }

    // in-register stages: element bit br (0..3) -> qubit 21-br
    #pragma unroll
    for (int br = 0; br < 4; br++) {
        int q = 21 - br;
        float c = cs1s[q][0], sn = cs1s[q][1];
        #pragma unroll
        for (int i0 = 0; i0 < 16; i0++) if (!(i0 & (1 << br))) {
            int i1 = i0 | (1 << br);
            float a0 = r[i0], a1 = r[i1];
            r[i0] = c * a0 - sn * a1;
            r[i1] = sn * a0 + c * a1;
        }
    }
    // shuffle stages: element bit 4+lb -> qubit 17-lb
    #pragma unroll
    for (int lb = 0; lb < 5; lb++) {
        int q = 17 - lb;
        float c = cs1s[q][0], sn = cs1s[q][1];
        float ss = (lane & (1 << lb)) ? sn : -sn;
        #pragma unroll
        for (int i = 0; i < 16; i++) {
            float p = __shfl_xor_sync(0xffffffffu, r[i], 1 << lb);
            r[i] = fmaf(ss, p, c * r[i]);
        }
    }
    __syncthreads();   // tables no longer needed

    // swizzled exchange: rotate bits 9..12 into the register index
    #pragma unroll
    for (int i = 0; i < 16; i++) {
        unsigned o = (unsigned)(t * 16 + i);
        s[o ^ ((o >> 5) & 31u)] = r[i];
    }
    __syncthreads();
    #pragma unroll
    for (int j = 0; j < 16; j++) {
        unsigned o = ((unsigned)j << 9) | (unsigned)t;
        r[j] = s[o ^ ((o >> 5) & 31u)];
    }
    // in-register stages: element bit 9+bj -> qubit 12-bj
    #pragma unroll
    for (int bj = 0; bj < 4; bj++) {
        int q = 12 - bj;
        float c = cs1s[q][0], sn = cs1s[q][1];
        #pragma unroll
        for (int j0 = 0; j0 < 16; j0++) if (!(j0 & (1 << bj))) {
            int j1 = j0 | (1 << bj);
            float a0 = r[j0], a1 = r[j1];
            r[j0] = c * a0 - sn * a1;
            r[j1] = sn * a0 + c * a1;
        }
    }
    float* __restrict__ g = st ? g_psi1 : g_psi0;
    #pragma unroll
    for (int j = 0; j < 16; j++)
        g[base + ((unsigned)j << 9) + (unsigned)t] = r[j];
}

// ---------------- kernel 2: layer-2 RY on bits 13..21, register-blocked ----------------
__global__ void __launch_bounds__(512, 2) k_passB(const float* __restrict__ theta) {
    __shared__ float s[512 * 17];
    __shared__ float cs1s[NQ][2];
    int bx = blockIdx.x;
    int st = bx >> 9;
    unsigned mid = (unsigned)(bx & 511) << 4;
    float* __restrict__ g = st ? g_psi1 : g_psi0;
    int t = threadIdx.x;
    int lane = t & 31, w = t >> 5;   // w = 0..15

    if (t < NQ) {
        float h1 = 0.5f * theta[NQ + t];
        cs1s[t][0] = cosf(h1); cs1s[t][1] = sinf(h1);
    }

    const float4* G4 = (const float4*)g;
    for (int v = t; v < 2048; v += 512) {
        int hi = v >> 2, q = v & 3;
        float4 d = G4[((unsigned)hi << 11) + (mid >> 2) + (unsigned)q];
        int sb = hi * 17 + q * 4;
        s[sb + 0] = d.x; s[sb + 1] = d.y; s[sb + 2] = d.z; s[sb + 3] = d.w;
    }
    __syncthreads();

    float r[16];
    #pragma unroll
    for (int j = 0; j < 16; j++)
        r[j] = s[((j << 5) | lane) * 17 + w];

    #pragma unroll
    for (int lb = 0; lb < 5; lb++) {
        int q = 8 - lb;
        float c = cs1s[q][0], sn = cs1s[q][1];
        float ss = (lane & (1 << lb)) ? sn : -sn;
        #pragma unroll
        for (int j = 0; j < 16; j++) {
            float p = __shfl_xor_sync(0xffffffffu, r[j], 1 << lb);
            r[j] = fmaf(ss, p, c * r[j]);
        }
    }
    #pragma unroll
    for (int bj = 0; bj < 4; bj++) {
        int q = 3 - bj;
        float c = cs1s[q][0], sn = cs1s[q][1];
        #pragma unroll
        for (int j0 = 0; j0 < 16; j0++) if (!(j0 & (1 << bj))) {
            int j1 = j0 | (1 << bj);
            float a0 = r[j0], a1 = r[j1];
            r[j0] = c * a0 - sn * a1;
            r[j1] = sn * a0 + c * a1;
        }
    }
    #pragma unroll
    for (int j = 0; j < 16; j++)
        s[((j << 5) | lane) * 17 + w] = r[j];
    __syncthreads();

    float4* GW4 = (float4*)g;
    for (int v = t; v < 2048; v += 512) {
        int hi = v >> 2, q = v & 3;
        int sb = hi * 17 + q * 4;
        float4 d = make_float4(s[sb + 0], s[sb + 1], s[sb + 2], s[sb + 3]);
        GW4[((unsigned)hi << 11) + (mid >> 2) + (unsigned)q] = d;
    }
}

// ---------------- kernel 3: register-blocked Pauli reductions ----------------
// Slot layout (group-ordered tree reduction):
//   0 Se, 1 Sf ; 2+k Ze_k, 14+k Zf_k (k=0..11)
//   m20:26..28  m19:29..31            (group 0 = slots 0..31)
//   m18:32..34  m17..13:35+3*(17-m)  m12..10:50+3*(12-m)  m0:59..62
//                                      (group 1 = slots 32..63)
//   m1..9:64+3*(m-1) (ad,U,V)  m21:91..94   (group 2 = slots 64..95)
__global__ void __launch_bounds__(256, 3) k_reduce() {
    __shared__ float s0[4096];
    __shared__ float s1[4096];
    __shared__ float sacc[8][96];
    unsigned tile = blockIdx.x;
    unsigned base = tile << 12;
    int t = threadIdx.x, w = t >> 5, lane = t & 31;
    int c = t;

    float acc[96];
    #pragma unroll
    for (int k = 0; k < 96; k++) acc[k] = 0.f;

    float r0[16], r1[16];
    {
        const float4* G0 = (const float4*)(g_psi0 + base);
        const float4* G1 = (const float4*)(g_psi1 + base);
        float4* S0 = (float4*)s0;
        float4* S1 = (float4*)s1;
        #pragma unroll
        for (int q = 0; q < 4; q++) {
            float4 a = G0[c * 4 + q]; S0[c * 4 + q] = a;
            r0[q*4+0] = a.x; r0[q*4+1] = a.y; r0[q*4+2] = a.z; r0[q*4+3] = a.w;
            float4 b = G1[c * 4 + q]; S1[c * 4 + q] = b;
            r1[q*4+0] = b.x; r1[q*4+1] = b.y; r1[q*4+2] = b.z; r1[q*4+3] = b.w;
        }
    }
    unsigned H = ((unsigned)(__popc(t & 0xFF) & 1)) << 31;

    // batched tree reduce of 32 consecutive slots; lane l ends with slot base+l
    #define TREE32(BS) { \
        _Pragma("unroll") \
        for (int off = 16; off >= 1; off >>= 1) { \
            _Pragma("unroll") \
            for (int k = 0; k < off; k++) { \
                float send = (lane & off) ? acc[(BS)+k] : acc[(BS)+k+off]; \
                float recv = __shfl_xor_sync(0xffffffffu, send, off); \
                acc[(BS)+k] = ((lane & off) ? acc[(BS)+k+off] : acc[(BS)+k]) + recv; \
            } \
        } \
        sacc[w][(BS) + lane] = acc[(BS)]; \
    }

    #define ZFOLD(EXPR, IDXBASE, TOTIDX) { \
        float x[16]; \
        _Pragma("unroll") for (int i = 0; i < 16; i++) x[i] = (EXPR); \
        float s1a[8], d0[8]; \
        _Pragma("unroll") for (int j = 0; j < 8; j++) { \
            s1a[j] = x[2*j] + x[2*j+1]; d0[j] = x[2*j] - x[2*j+1]; } \
        float D0 = sf8(d0), D1 = sf8(s1a); \
        float s2[4]; \
        _Pragma("unroll") for (int j = 0; j < 4; j++) s2[j] = s1a[2*j] + s1a[2*j+1]; \
        float D2 = sf4(s2); \
        float s3a = s2[0] + s2[1], s3b = s2[2] + s2[3]; \
        float D3 = s3a - s3b, T = s3a + s3b; \
        acc[(IDXBASE)+0] = sgnx(D0, H); \
        acc[(IDXBASE)+1] = sgnx(D1, H); \
        acc[(IDXBASE)+2] = sgnx(D2, H); \
        acc[(IDXBASE)+3] = sgnx(D3, H); \
        _Pragma("unroll") for (int k = 4; k < 12; k++) { \
            unsigned hk = ((unsigned)(__popc((unsigned)t >> (k-4)) & 1)) << 31; \
            acc[(IDXBASE)+k] = sgnx(T, hk); } \
        acc[TOTIDX] = T; }

    ZFOLD(r0[i]*r0[i] - r1[i]*r1[i], 2, 0)
    ZFOLD(r0[i]*r1[i], 14, 1)
    #undef ZFOLD

    #define INREG(SLOT, MSK, PB) { \
        float ad = 0.f, us = 0.f, wr = 0.f; \
        _Pragma("unroll") for (int i = 0; i < 16; i++) { \
            float p0 = r0[i ^ (MSK)], p1 = r1[i ^ (MSK)]; \
            ad += r0[i]*p0 - r1[i]*p1; \
            float u = r0[i]*p1; us += u; \
            if (__popc(i >> (PB)) & 1) wr -= u; else wr += u; } \
        acc[(SLOT)+0] = ad; acc[(SLOT)+1] = us; acc[(SLOT)+2] = sgnx(wr, H); }
    INREG(26, 3, 1)    // m=20
    INREG(29, 6, 2)    // m=19
    TREE32(0)          // group 0 complete
    INREG(32, 12, 3)   // m=18
    #undef INREG

    #define SHFM(SLOT, MM, LX, IX) { \
        float ad = 0.f, us = 0.f; \
        _Pragma("unroll") for (int i = 0; i < 16; i++) { \
            float p0 = __shfl_xor_sync(0xffffffffu, r0[i ^ (IX)], (LX)); \
            float p1 = __shfl_xor_sync(0xffffffffu, r1[i ^ (IX)], (LX)); \
            ad += r0[i]*p0 - r1[i]*p1; us += r0[i]*p1; } \
        unsigned hs = ((unsigned)(__popc((unsigned)t >> (21-(MM)-4)) & 1)) << 31; \
        acc[(SLOT)+0] = ad; acc[(SLOT)+1] = us; acc[(SLOT)+2] = sgnx(us, hs); }
    SHFM(35, 17, 1, 8)
    SHFM(38, 16, 3, 0)
    SHFM(41, 15, 6, 0)
    SHFM(44, 14, 12, 0)
    SHFM(47, 13, 24, 0)
    #undef SHFM

    __syncthreads();

    #define SMEMM(SLOT, MM, CX) { \
        float ad = 0.f, us = 0.f; \
        const float4* S04 = (const float4*)s0; \
        const float4* S14 = (const float4*)s1; \
        _Pragma("unroll") for (int q = 0; q < 4; q++) { \
            float4 a = S04[(c ^ (CX)) * 4 + q], b = S14[(c ^ (CX)) * 4 + q]; \
            float pa[4] = {a.x, a.y, a.z, a.w}; \
            float pb[4] = {b.x, b.y, b.z, b.w}; \
            _Pragma("unroll") for (int z = 0; z < 4; z++) { \
                int i = q*4 + z; \
                ad += r0[i]*pa[z] - r1[i]*pb[z]; us += r0[i]*pb[z]; } } \
        unsigned hs = ((unsigned)(__popc((unsigned)t >> (21-(MM)-4)) & 1)) << 31; \
        acc[(SLOT)+0] = ad; acc[(SLOT)+1] = us; acc[(SLOT)+2] = sgnx(us, hs); }
    SMEMM(50, 12, 0x30)
    SMEMM(53, 11, 0x60)
    SMEMM(56, 10, 0xC0)
    #undef SMEMM

    #define CROSSM(SLOT, DH, CH, SWAP, DOW, CONDBIT) \
    if (!(base & (CONDBIT))) { \
        float ad = 0.f, U = 0.f, V = 0.f, wr = 0.f; \
        const float4* P0 = (const float4*)(g_psi0 + (base ^ (DH))); \
        const float4* P1 = (const float4*)(g_psi1 + (base ^ (DH))); \
        _Pragma("unroll") for (int q = 0; q < 4; q++) { \
            float4 a = P0[(c ^ (CH)) * 4 + q], b = P1[(c ^ (CH)) * 4 + q]; \
            float pa[4] = {a.x, a.y, a.z, a.w}; \
            float pb[4] = {b.x, b.y, b.z, b.w}; \
            _Pragma("unroll") for (int z = 0; z < 4; z++) { \
                int i = q*4 + z; int zz = (SWAP) ? (z ^ 1) : z; \
                float p0 = pa[zz], p1 = pb[zz]; \
                ad += r0[i]*p0 - r1[i]*p1; \
                float u = r0[i]*p1, vv = p0*r1[i]; \
                U += u; V += vv; \
                if (DOW) { if (__popc(i) & 1) wr -= (u - vv); else wr += (u - vv); } } } \
        acc[(SLOT)+0] = ad; acc[(SLOT)+1] = U; acc[(SLOT)+2] = V; \
        if (DOW) acc[(SLOT)+3] = sgnx(wr, H); }

    CROSSM(59, 0x300000u, 0, 0, 1, 0x200000u)      // m=0
    TREE32(32)                                     // group 1 complete
    CROSSM(64, (3u<<19), 0, 0, 0, (1u<<20))        // m=1
    CROSSM(67, (3u<<18), 0, 0, 0, (1u<<19))        // m=2
    CROSSM(70, (3u<<17), 0, 0, 0, (1u<<18))        // m=3
    CROSSM(73, (3u<<16), 0, 0, 0, (1u<<17))        // m=4
    CROSSM(76, (3u<<15), 0, 0, 0, (1u<<16))        // m=5
    CROSSM(79, (3u<<14), 0, 0, 0, (1u<<15))        // m=6
    CROSSM(82, (3u<<13), 0, 0, 0, (1u<<14))        // m=7
    CROSSM(85, (3u<<12), 0, 0, 0, (1u<<13))        // m=8
    CROSSM(88, 0x1000u, 0x80, 0, 0, (1u<<12))      // m=9
    CROSSM(91, 0x300000u, 0, 1, 1, 0x200000u)      // m=21
    TREE32(64)                                     // group 2 complete
    #undef CROSSM
    #undef TREE32

    __syncthreads();

    if (t < 96) {
        float a = 0.f;
        #pragma unroll
        for (int r = 0; r < 8; r++) a += sacc[r][t];
        sacc[0][t] = a;
    }
    __syncthreads();

    if (t < 22) {
        int m = t;
        const float* S = sacc[0];
        unsigned Pm = (m == 0) ? 0x1FFFFFu : (((1u << (m + 1)) - 1u) << (21 - m));
        float s = (__popc(base & Pm) & 1) ? -1.f : 1.f;
        float cd, c01, ad, a01, b01;
        if (m >= 10 && m <= 20) {
            int k = 21 - m;
            cd = s * S[2 + k]; c01 = s * S[14 + k];
            int b = (m >= 18) ? (26 + 3 * (20 - m))
                  : (m >= 13) ? (35 + 3 * (17 - m))
                              : (50 + 3 * (12 - m));
            ad = S[b]; a01 = S[b + 1]; b01 = -s * S[b + 2];
        } else if (m >= 1 && m <= 9) {
            cd = s * S[0]; c01 = s * S[1];
            if (base & (1u << (21 - m))) {
                ad = 0.f; a01 = 0.f; b01 = 0.f;
            } else {
                int sl = 64 + 3 * (m - 1);
                float U = S[sl + 1], V = S[sl + 2];
                ad = 2.f * S[sl];
                a01 = U + V;
                b01 = -s * (U - V);
            }
        } else if (m == 0) {
            cd = s * S[2]; c01 = s * S[14];
            if (base & 0x200000u) { ad = 0.f; a01 = 0.f; b01 = 0.f; }
            else {
                ad = 2.f * S[59];
                a01 = S[60] + S[61];
                b01 = -s * S[62];
            }
        } else { // m == 21
            cd = s * S[2]; c01 = s * S[14];
            if (base & 0x200000u) { ad = 0.f; a01 = 0.f; b01 = 0.f; }
            else {
                ad = 2.f * S[91];
                a01 = S[92] + S[93];
                b01 = -s * S[94];
            }
        }
        float* pp = &g_sums[(unsigned)m * 5];
        atomicAdd(&pp[0], ad);
        atomicAdd(&pp[1], a01);
        atomicAdd(&pp[2], b01);
        atomicAdd(&pp[3], cd);
        atomicAdd(&pp[4], c01);
    }
}

// ---------------- kernel 4: final combine (single warp) ----------------
__global__ void k_final(float* __restrict__ out) {
    int lane = threadIdx.x;
    float term = 0.f;
    if (lane < 22) {
        const float* S = g_sums + lane * 5;
        float ad = S[0], a01 = S[1], b01 = S[2], cd = S[3], c01 = S[4];
        term = 0.5f * ad * ad + 2.f * a01 * a01
             + 2.f * b01 * b01
             + 0.5f * cd * cd + 2.f * c01 * c01;
    }
    term = wred(term);
    if (lane == 0) out[0] = term;
}

extern "C" void kernel_launch(void* const* d_in, const int* in_sizes, int n_in,
                              void* d_out, int out_size) {
    const float* theta = (const float*)d_in[0];
    (void)in_sizes; (void)n_in; (void)out_size;
    k_genA<<<1024, 512>>>(theta);
    k_passB<<<1024, 512>>>(theta);
    k_reduce<<<1024, 256>>>();
    k_final<<<1, 32>>>((float*)d_out);
}